// round 13
// baseline (speedup 1.0000x reference)
#include <cuda_runtime.h>
#include <cuda_fp16.h>
#include <math.h>
#include <stdint.h>

#define BB   64
#define LL   512
#define EE   256
#define PR   128          // pos feature width (2*P)
#define KK   512
#define TT   53
#define SR   516          // padded rows (2-halo)
#define NCH  26           // K-chunks of 64 per l0 tile (20 embed + 6 pos)
#define NGI  (4 * NCH)    // flattened chunk count (4 l0 tiles)
#define NST  3            // stage slots
#define STAGE_B 32768     // A(16KB) + B(16KB) per chunk slot
#define SMEM_CONV (NST * STAGE_B + 1024)

// ---------------- static device scratch ----------------
__device__ __align__(16) __half g_Eh[BB * SR * EE];    // [b][l+2][e] fp16
__device__ __align__(16) __half g_Ph[BB * SR * PR];    // [b][l+1][p] fp16
__device__ __align__(16) __half g_Wh[5 * KK * EE];     // [d][k][e] fp16
__device__ __align__(16) __half g_Wph[3 * KK * PR];    // [t][k][p] fp16
__device__ __align__(16) float  g_corr0[BB * KK];
__device__ __align__(16) float  g_corrL[BB * KK];
__device__ __align__(16) float  g_pooled[BB * KK];
__device__ __align__(16) float  g_com[BB * 2048];      // subj(768) obj(768) sent_h(512)

// ---------------- helpers ----------------
__device__ __forceinline__ uint32_t smem_u32(const void* p) {
    uint32_t a;
    asm("{ .reg .u64 t; cvta.to.shared.u64 t, %1; cvt.u32.u64 %0, t; }" : "=r"(a) : "l"(p));
    return a;
}
#define SWZ(off) ((off) ^ (((off) >> 3) & 0x70))
__device__ __forceinline__ void cpa16(uint32_t dst, const void* src) {
    asm volatile("cp.async.cg.shared.global [%0], [%1], 16;" :: "r"(dst), "l"(src) : "memory");
}
#define CP_COMMIT() asm volatile("cp.async.commit_group;" ::: "memory")
#define CP_WAIT(n)  asm volatile("cp.async.wait_group %0;" :: "n"(n) : "memory")
__device__ __forceinline__ void ldsm4(uint32_t* r, uint32_t addr) {
    asm volatile("ldmatrix.sync.aligned.m8n8.x4.shared.b16 {%0,%1,%2,%3}, [%4];"
                 : "=r"(r[0]), "=r"(r[1]), "=r"(r[2]), "=r"(r[3]) : "r"(addr));
}
__device__ __forceinline__ void mma16816(float* c, const uint32_t* a, uint32_t b0, uint32_t b1) {
    asm volatile("mma.sync.aligned.m16n8k16.row.col.f32.f16.f16.f32 "
                 "{%0,%1,%2,%3}, {%4,%5,%6,%7}, {%8,%9}, {%0,%1,%2,%3};"
                 : "+f"(c[0]), "+f"(c[1]), "+f"(c[2]), "+f"(c[3])
                 : "r"(a[0]), "r"(a[1]), "r"(a[2]), "r"(a[3]), "r"(b0), "r"(b1));
}

// ---------------- mega-prep: wprep [0,512) + gather [512,1536) + entcorr [1536,1600) ----------------
__global__ void __launch_bounds__(256) prep_kernel(const float* __restrict__ conv_w,
                                                   const int* __restrict__ context,
                                                   const int* __restrict__ sdis,
                                                   const int* __restrict__ odis,
                                                   const float* __restrict__ etab,
                                                   const float* __restrict__ ptab,
                                                   const int* __restrict__ sidx,
                                                   const int* __restrict__ oidx) {
    __shared__ float smbuf[4096];                 // 16KB: wprep row / entcorr weights
    const int tid = threadIdx.x;
    if (blockIdx.x < 512) {
        // ---- weight fold+transpose: one block per k ----
        const int k = blockIdx.x;
        const float* src = conv_w + (size_t)k * 2688;
        for (int i = tid; i < 2688; i += 256) smbuf[i] = src[i];
        __syncthreads();
        const int e = tid;
#pragma unroll
        for (int d = 0; d < 5; ++d) {
            float s = 0.f;
#pragma unroll
            for (int j = 0; j < 3; ++j) {
                int t = d - j;
                if (t >= 0 && t < 3) s += smbuf[(j * EE + e) * 3 + t];
            }
            g_Wh[((size_t)d * KK + k) * EE + e] = __float2half(s);
        }
        if (tid < PR) {
#pragma unroll
            for (int t = 0; t < 3; ++t)
                g_Wph[((size_t)t * KK + k) * PR + tid] = __float2half(smbuf[(768 + tid) * 3 + t]);
        }
    } else if (blockIdx.x < 1536) {
        // ---- gather + halo zeroing ----
        const int bx = blockIdx.x - 512;
        const int b = bx >> 4, xt = bx & 15;
        const int grp = tid >> 5, lane = tid & 31;
        __half* Eb = g_Eh + (size_t)b * SR * EE;
        __half* Pb = g_Ph + (size_t)b * SR * PR;
#pragma unroll
        for (int li = 0; li < 4; ++li) {
            int l = xt * 32 + grp * 4 + li;
            int row = b * LL + l;
            int tok = context[row];
            const float4* es4 = (const float4*)(etab + (size_t)tok * EE);
            uint2* Erow = (uint2*)(Eb + (size_t)(l + 2) * EE);
#pragma unroll
            for (int it = 0; it < 2; ++it) {
                int j = it * 32 + lane;
                float4 f = es4[j];
                __half2 h01 = __floats2half2_rn(f.x, f.y);
                __half2 h23 = __floats2half2_rn(f.z, f.w);
                uint2 u;
                u.x = *(uint32_t*)&h01; u.y = *(uint32_t*)&h23;
                Erow[j] = u;
            }
            int ds = sdis[row], od = odis[row];
            uint2* Prow = (uint2*)(Pb + (size_t)(l + 1) * PR);
            {
                int j = lane;
                float4 f = (j < 16) ? ((const float4*)(ptab + (size_t)ds * 64))[j]
                                    : ((const float4*)(ptab + (size_t)od * 64))[j - 16];
                __half2 h01 = __floats2half2_rn(f.x, f.y);
                __half2 h23 = __floats2half2_rn(f.z, f.w);
                uint2 u;
                u.x = *(uint32_t*)&h01; u.y = *(uint32_t*)&h23;
                Prow[j] = u;
            }
        }
        if (xt == 0) {
            const __half2 z = __floats2half2_rn(0.f, 0.f);
            const int erows[4] = {0, 1, 514, 515};
            const int prows[4] = {0, 513, 514, 515};
#pragma unroll
            for (int i = 0; i < 2; ++i) {
                int idx = tid + i * 256;
                ((__half2*)Eb)[(size_t)erows[idx >> 7] * 128 + (idx & 127)] = z;
            }
            ((__half2*)Pb)[(size_t)prows[tid >> 6] * 64 + (tid & 63)] = z;
        }
    } else {
        // ---- entity features (b = bx) + corrections (k in [bx*8, bx*8+8)) ----
        const int bx = blockIdx.x - 1536;
        const int w = tid >> 5, lane = tid & 31;
        // stage correction weight rows into smem: w0s = smbuf[0..2047], wLs = smbuf[2048..]
        {
            const int k = bx * 8 + w;
            const float* wk = conv_w + (size_t)k * 2688;
            for (int i = lane; i < EE; i += 32) {
                smbuf[w * 256 + i]        = wk[(2 * EE + i) * 3 + 0];   // C0w
                smbuf[2048 + w * 256 + i] = wk[i * 3 + 2];              // CLw
            }
        }
        // entity features directly from etab (exact fp32, matches reference)
        {
            const int b = bx, e = tid;
            for (int ent = 0; ent < 2; ++ent) {
                const int* ix = ent ? oidx : sidx;
                int s = ix[b * 2 + 0], en = ix[b * 2 + 1];
                int lo = s < 0 ? 0 : s;
                int hi = en > LL - 1 ? LL - 1 : en;
                float sum = 0.f; int cnt = 0;
                for (int l = lo; l <= hi; ++l) {
                    int tok = context[b * LL + l];
                    sum += etab[(size_t)tok * EE + e]; ++cnt;
                }
                float mean = sum / (float)cnt;
                int li = s - 1; if (li < 0) li += LL;
                float left = etab[(size_t)context[b * LL + li] * EE + e];
                float right = 0.f;
                if (en + 1 < LL) {
                    int ri = en + 1; if (ri < 0) ri = 0;
                    right = etab[(size_t)context[b * LL + ri] * EE + e];
                }
                float* dst = g_com + (size_t)b * 2048 + ent * 768;
                dst[e] = mean; dst[256 + e] = left; dst[512 + e] = right;
            }
        }
        __syncthreads();
        // corrections: warp per k, e0/eL read from etab via context
        const int k = bx * 8 + w;
        for (int b = 0; b < BB; ++b) {
            int tok0 = context[b * LL + 0];
            int tokL = context[b * LL + LL - 1];
            const float* e0 = etab + (size_t)tok0 * EE;
            const float* eL = etab + (size_t)tokL * EE;
            float s0 = 0.f, sL = 0.f;
#pragma unroll
            for (int q = 0; q < 8; ++q) {
                int e = lane + q * 32;
                s0 += e0[e] * smbuf[w * 256 + e];
                sL += eL[e] * smbuf[2048 + w * 256 + e];
            }
#pragma unroll
            for (int o = 16; o; o >>= 1) {
                s0 += __shfl_xor_sync(0xFFFFFFFFu, s0, o);
                sL += __shfl_xor_sync(0xFFFFFFFFu, sL, o);
            }
            if (lane == 0) {
                g_corr0[(size_t)b * KK + k] = s0;
                g_corrL[(size_t)b * KK + k] = sL;
            }
        }
    }
}

// ---------------- fp16 mma conv + fused max-pool (4 warps, 64x64 warp tile) ----------------
__device__ __forceinline__ void stage_chunk(int gi, uint32_t sbase,
                                            const __half* Eb, const __half* Pb,
                                            int k0, int tid) {
    int l0 = (gi / NCH) * 128;
    int c  = gi % NCH;
    const __half* as; const __half* bs; int astr, bstr;
    if (c < 20) {
        int d = c >> 2, ec = c & 3;
        as = Eb + (size_t)(l0 + d) * EE + ec * 64;               astr = EE;
        bs = g_Wh + ((size_t)d * KK + k0) * EE + ec * 64;        bstr = EE;
    } else {
        int cc = c - 20, t = cc >> 1, pc = cc & 1;
        as = Pb + (size_t)(l0 + t) * PR + pc * 64;               astr = PR;
        bs = g_Wph + ((size_t)t * KK + k0) * PR + pc * 64;       bstr = PR;
    }
    const uint32_t st = sbase + (uint32_t)(gi % NST) * STAGE_B;
#pragma unroll
    for (int i = 0; i < 8; ++i) {
        int id = tid + i * 128;
        int r = id >> 3, c16 = id & 7;
        uint32_t off = SWZ((uint32_t)(r * 128 + c16 * 16));
        cpa16(st + off,         (const char*)(as + (size_t)r * astr) + c16 * 16);
        cpa16(st + 16384 + off, (const char*)(bs + (size_t)r * bstr) + c16 * 16);
    }
}

__global__ void __launch_bounds__(128, 2) conv_mma_kernel(const float* __restrict__ conv_b) {
    extern __shared__ char smem[];
    const uint32_t sbase = smem_u32(smem);
    float* red = (float*)(smem + NST * STAGE_B);
    const int tid = threadIdx.x, wid = tid >> 5, lane = tid & 31;
    const int lw = wid >> 1;          // 0..1 : 64 l-rows
    const int kw = wid & 1;           // 0..1 : 64 k-cols
    const int b = blockIdx.y, k0 = blockIdx.x * 128;
    const __half* Eb = g_Eh + (size_t)b * SR * EE;
    const __half* Pb = g_Ph + (size_t)b * SR * PR;

    const int rquad = lane >> 2, rlo = lane & 3;
    const int rowA = lw * 64 + (lane & 7) + ((lane >> 3) & 1) * 8;
    const int rowB = kw * 64 + (lane & 7) + ((lane >> 3) & 1) * 8;
    const int kbl  = (lane >> 4) * 16;

    float acc[4][8][4];
    float colmax[8][2];
#pragma unroll
    for (int nt = 0; nt < 8; ++nt) { colmax[nt][0] = -3.4e38f; colmax[nt][1] = -3.4e38f; }

    stage_chunk(0, sbase, Eb, Pb, k0, tid); CP_COMMIT();
    stage_chunk(1, sbase, Eb, Pb, k0, tid); CP_COMMIT();

    for (int gi = 0; gi < NGI; ++gi) {
        if (gi == NGI - 1) { CP_WAIT(0); } else { CP_WAIT(1); }
        __syncthreads();
        if (gi + 2 < NGI) { stage_chunk(gi + 2, sbase, Eb, Pb, k0, tid); CP_COMMIT(); }
        if (gi % NCH == 0) {
#pragma unroll
            for (int mt = 0; mt < 4; ++mt)
#pragma unroll
                for (int nt = 0; nt < 8; ++nt)
#pragma unroll
                    for (int j = 0; j < 4; ++j) acc[mt][nt][j] = 0.f;
        }
        const uint32_t sA = sbase + (uint32_t)(gi % NST) * STAGE_B;
        const uint32_t sB = sA + 16384;
#pragma unroll
        for (int ks = 0; ks < 4; ++ks) {
            uint32_t a[4][4], bf[4][4];
#pragma unroll
            for (int mt = 0; mt < 4; ++mt)
                ldsm4(a[mt], sA + SWZ((uint32_t)((rowA + mt * 16) * 128 + ks * 32 + kbl)));
#pragma unroll
            for (int bt = 0; bt < 4; ++bt)
                ldsm4(bf[bt], sB + SWZ((uint32_t)((rowB + bt * 16) * 128 + ks * 32 + kbl)));
#pragma unroll
            for (int mt = 0; mt < 4; ++mt)
#pragma unroll
                for (int bt = 0; bt < 4; ++bt) {
                    mma16816(acc[mt][bt * 2 + 0], a[mt], bf[bt][0], bf[bt][2]);
                    mma16816(acc[mt][bt * 2 + 1], a[mt], bf[bt][1], bf[bt][3]);
                }
        }
        if (gi % NCH == NCH - 1) {
            const int l0 = (gi / NCH) * 128;
            if (l0 == 0 && lw == 0 && rquad == 0) {        // global row 0
#pragma unroll
                for (int nt = 0; nt < 8; ++nt) {
                    int n = k0 + kw * 64 + nt * 8 + rlo * 2;
                    acc[0][nt][0] -= g_corr0[(size_t)b * KK + n];
                    acc[0][nt][1] -= g_corr0[(size_t)b * KK + n + 1];
                }
            }
            if (l0 == 384 && lw == 1 && rquad == 7) {      // global row 511
#pragma unroll
                for (int nt = 0; nt < 8; ++nt) {
                    int n = k0 + kw * 64 + nt * 8 + rlo * 2;
                    acc[3][nt][2] -= g_corrL[(size_t)b * KK + n];
                    acc[3][nt][3] -= g_corrL[(size_t)b * KK + n + 1];
                }
            }
#pragma unroll
            for (int mt = 0; mt < 4; ++mt)
#pragma unroll
                for (int nt = 0; nt < 8; ++nt) {
                    colmax[nt][0] = fmaxf(colmax[nt][0], fmaxf(acc[mt][nt][0], acc[mt][nt][2]));
                    colmax[nt][1] = fmaxf(colmax[nt][1], fmaxf(acc[mt][nt][1], acc[mt][nt][3]));
                }
        }
    }
#pragma unroll
    for (int nt = 0; nt < 8; ++nt)
#pragma unroll
        for (int j = 0; j < 2; ++j) {
            float v = colmax[nt][j];
            v = fmaxf(v, __shfl_xor_sync(0xFFFFFFFFu, v, 4));
            v = fmaxf(v, __shfl_xor_sync(0xFFFFFFFFu, v, 8));
            v = fmaxf(v, __shfl_xor_sync(0xFFFFFFFFu, v, 16));
            if (rquad == 0)
                red[lw * 128 + kw * 64 + nt * 8 + rlo * 2 + j] = v;
        }
    __syncthreads();
    if (tid < 128)
        g_pooled[(size_t)b * KK + k0 + tid] =
            fmaxf(red[tid], red[128 + tid]) + conv_b[k0 + tid];
}

// ---------------- lin1: 64x4 grid, smem pooled tile, 16 ILP accumulators ----------------
__global__ void __launch_bounds__(256) lin1_kernel(const float* __restrict__ w1,
                                                   const float* __restrict__ b1) {
    const int tid = threadIdx.x;
    const int w = tid >> 5, lane = tid & 31;
    const int h = blockIdx.x * 8 + w;             // 64 h-groups x 8 warps
    const int b0 = blockIdx.y * 16;               // 4 b-groups x 16 batches
    __shared__ float pt[16 * 512];                // 32KB
#pragma unroll
    for (int i = 0; i < 32; ++i) {
        int idx = tid + i * 256;
        pt[idx] = g_pooled[(size_t)(b0 + (idx >> 9)) * KK + (idx & 511)];
    }
    const float4* w4 = (const float4*)(w1 + (size_t)h * KK);
    float4 f[4];
#pragma unroll
    for (int q = 0; q < 4; ++q) f[q] = w4[lane + q * 32];
    __syncthreads();
    const float4* p4 = (const float4*)pt;
    float s[16];
#pragma unroll
    for (int i = 0; i < 16; ++i) s[i] = 0.f;
#pragma unroll
    for (int q = 0; q < 4; ++q) {
        int j = lane + q * 32;
#pragma unroll
        for (int i = 0; i < 16; ++i) {
            float4 g = p4[i * 128 + j];
            s[i] += f[q].x * g.x + f[q].y * g.y + f[q].z * g.z + f[q].w * g.w;
        }
    }
#pragma unroll
    for (int o = 16; o; o >>= 1)
#pragma unroll
        for (int i = 0; i < 16; ++i)
            s[i] += __shfl_xor_sync(0xFFFFFFFFu, s[i], o);
    if (lane == 0) {
        const float bb = b1[h];
#pragma unroll
        for (int i = 0; i < 16; ++i)
            g_com[(size_t)(b0 + i) * 2048 + 1536 + h] = tanhf(s[i] + bb);
    }
}

// ---------------- scores: 53 blocks, 8 ILP accumulators per warp ----------------
__global__ void __launch_bounds__(256) scores_kernel(const float* __restrict__ w2,
                                                     const float* __restrict__ b2,
                                                     float* __restrict__ out) {
    const int t = blockIdx.x, tid = threadIdx.x;
    const int w = tid >> 5, lane = tid & 31;
    __shared__ float wrow[2048];
    for (int i = tid; i < 2048; i += 256) wrow[i] = w2[(size_t)t * 2048 + i];
    __syncthreads();
    const float4* w4 = (const float4*)wrow;
    float s[8];
#pragma unroll
    for (int i = 0; i < 8; ++i) s[i] = 0.f;
#pragma unroll
    for (int q = 0; q < 16; ++q) {
        int j = lane + q * 32;
        float4 f = w4[j];
#pragma unroll
        for (int bi = 0; bi < 8; ++bi) {
            const float4* c4 = (const float4*)(g_com + (size_t)(w * 8 + bi) * 2048);
            float4 g = c4[j];
            s[bi] += f.x * g.x + f.y * g.y + f.z * g.z + f.w * g.w;
        }
    }
#pragma unroll
    for (int o = 16; o; o >>= 1)
#pragma unroll
        for (int bi = 0; bi < 8; ++bi)
            s[bi] += __shfl_xor_sync(0xFFFFFFFFu, s[bi], o);
    if (lane == 0) {
        const float bb = b2[t];
#pragma unroll
        for (int bi = 0; bi < 8; ++bi)
            out[(size_t)(w * 8 + bi) * TT + t] = s[bi] + bb;
    }
}

// ---------------- launch ----------------
extern "C" void kernel_launch(void* const* d_in, const int* in_sizes, int n_in,
                              void* d_out, int out_size) {
    const int*   context = (const int*)  d_in[0];
    const int*   sidx    = (const int*)  d_in[1];
    const int*   oidx    = (const int*)  d_in[2];
    const int*   sdis    = (const int*)  d_in[3];
    const int*   odis    = (const int*)  d_in[4];
    const float* etab    = (const float*)d_in[5];
    const float* ptab    = (const float*)d_in[6];
    const float* conv_w  = (const float*)d_in[7];
    const float* conv_b  = (const float*)d_in[8];
    const float* lin1_w  = (const float*)d_in[9];
    const float* lin1_b  = (const float*)d_in[10];
    const float* lin2_w  = (const float*)d_in[11];
    const float* lin2_b  = (const float*)d_in[12];
    float* out = (float*)d_out;

    cudaFuncSetAttribute(conv_mma_kernel,
                         cudaFuncAttributeMaxDynamicSharedMemorySize, SMEM_CONV);

    prep_kernel<<<1600, 256>>>(conv_w, context, sdis, odis, etab, ptab, sidx, oidx);
    conv_mma_kernel<<<dim3(4, BB), 128, SMEM_CONV>>>(conv_b);
    lin1_kernel<<<dim3(64, 4), 256>>>(lin1_w, lin1_b);
    scores_kernel<<<TT, 256>>>(lin2_w, lin2_b, out);
}

// round 14
// speedup vs baseline: 1.2645x; 1.2645x over previous
#include <cuda_runtime.h>
#include <cuda_fp16.h>
#include <math.h>
#include <stdint.h>

#define BB   64
#define LL   512
#define EE   256
#define PR   128          // pos feature width (2*P)
#define KK   512
#define TT   53
#define SR   516          // padded rows (2-halo)
#define NCH  26           // K-chunks of 64 per l0 tile (20 embed + 6 pos)
#define NGI  (4 * NCH)    // flattened chunk count (4 l0 tiles)
#define NST  3            // stage slots
#define STAGE_B 32768     // A(16KB) + B(16KB) per chunk slot
#define SMEM_CONV (NST * STAGE_B + 1024)
#define SMEM_CORR (2 * 64 * 256 * 4)   // 128KB

// ---------------- static device scratch ----------------
__device__ __align__(16) __half g_Eh[BB * SR * EE];    // [b][l+2][e] fp16
__device__ __align__(16) __half g_Ph[BB * SR * PR];    // [b][l+1][p] fp16
__device__ __align__(16) __half g_Wh[5 * KK * EE];     // [d][k][e] fp16
__device__ __align__(16) __half g_Wph[3 * KK * PR];    // [t][k][p] fp16
__device__ __align__(16) float  g_C0w[KK * EE];        // [k][e] fp32
__device__ __align__(16) float  g_CLw[KK * EE];        // [k][e] fp32
__device__ __align__(16) float  g_corr0[BB * KK];
__device__ __align__(16) float  g_corrL[BB * KK];
__device__ __align__(16) float  g_pooled[BB * KK];
__device__ __align__(16) float  g_com[BB * 2048];      // subj(768) obj(768) sent_h(512)

// ---------------- helpers ----------------
__device__ __forceinline__ uint32_t smem_u32(const void* p) {
    uint32_t a;
    asm("{ .reg .u64 t; cvta.to.shared.u64 t, %1; cvt.u32.u64 %0, t; }" : "=r"(a) : "l"(p));
    return a;
}
#define SWZ(off) ((off) ^ (((off) >> 3) & 0x70))
__device__ __forceinline__ void cpa16(uint32_t dst, const void* src) {
    asm volatile("cp.async.cg.shared.global [%0], [%1], 16;" :: "r"(dst), "l"(src) : "memory");
}
#define CP_COMMIT() asm volatile("cp.async.commit_group;" ::: "memory")
#define CP_WAIT(n)  asm volatile("cp.async.wait_group %0;" :: "n"(n) : "memory")
__device__ __forceinline__ void ldsm4(uint32_t* r, uint32_t addr) {
    asm volatile("ldmatrix.sync.aligned.m8n8.x4.shared.b16 {%0,%1,%2,%3}, [%4];"
                 : "=r"(r[0]), "=r"(r[1]), "=r"(r[2]), "=r"(r[3]) : "r"(addr));
}
__device__ __forceinline__ void mma16816(float* c, const uint32_t* a, uint32_t b0, uint32_t b1) {
    asm volatile("mma.sync.aligned.m16n8k16.row.col.f32.f16.f16.f32 "
                 "{%0,%1,%2,%3}, {%4,%5,%6,%7}, {%8,%9}, {%0,%1,%2,%3};"
                 : "+f"(c[0]), "+f"(c[1]), "+f"(c[2]), "+f"(c[3])
                 : "r"(a[0]), "r"(a[1]), "r"(a[2]), "r"(a[3]), "r"(b0), "r"(b1));
}

// ---------------- fused prep: wprep (blocks 0..511) + gather (blocks 512..1535) ----------------
__global__ void __launch_bounds__(256) prep_kernel(const float* __restrict__ conv_w,
                                                   const int* __restrict__ context,
                                                   const int* __restrict__ sdis,
                                                   const int* __restrict__ odis,
                                                   const float* __restrict__ etab,
                                                   const float* __restrict__ ptab) {
    const int tid = threadIdx.x;
    if (blockIdx.x < 512) {
        const int k = blockIdx.x;
        __shared__ float w[2688];
        const float* src = conv_w + (size_t)k * 2688;
        for (int i = tid; i < 2688; i += 256) w[i] = src[i];
        __syncthreads();
        const int e = tid;
#pragma unroll
        for (int d = 0; d < 5; ++d) {
            float s = 0.f;
#pragma unroll
            for (int j = 0; j < 3; ++j) {
                int t = d - j;
                if (t >= 0 && t < 3) s += w[(j * EE + e) * 3 + t];
            }
            g_Wh[((size_t)d * KK + k) * EE + e] = __float2half(s);
        }
        if (tid < PR) {
#pragma unroll
            for (int t = 0; t < 3; ++t)
                g_Wph[((size_t)t * KK + k) * PR + tid] = __float2half(w[(768 + tid) * 3 + t]);
        }
        g_C0w[(size_t)k * EE + e] = w[(2 * EE + e) * 3 + 0];
        g_CLw[(size_t)k * EE + e] = w[e * 3 + 2];
    } else {
        const int bx = blockIdx.x - 512;
        const int b = bx >> 4, xt = bx & 15;
        const int grp = tid >> 5, lane = tid & 31;
        __half* Eb = g_Eh + (size_t)b * SR * EE;
        __half* Pb = g_Ph + (size_t)b * SR * PR;
#pragma unroll
        for (int li = 0; li < 4; ++li) {
            int l = xt * 32 + grp * 4 + li;
            int row = b * LL + l;
            int tok = context[row];
            const float4* es4 = (const float4*)(etab + (size_t)tok * EE);
            uint2* Erow = (uint2*)(Eb + (size_t)(l + 2) * EE);
#pragma unroll
            for (int it = 0; it < 2; ++it) {
                int j = it * 32 + lane;
                float4 f = es4[j];
                __half2 h01 = __floats2half2_rn(f.x, f.y);
                __half2 h23 = __floats2half2_rn(f.z, f.w);
                uint2 u;
                u.x = *(uint32_t*)&h01; u.y = *(uint32_t*)&h23;
                Erow[j] = u;
            }
            int ds = sdis[row], od = odis[row];
            uint2* Prow = (uint2*)(Pb + (size_t)(l + 1) * PR);
            {
                int j = lane;
                float4 f = (j < 16) ? ((const float4*)(ptab + (size_t)ds * 64))[j]
                                    : ((const float4*)(ptab + (size_t)od * 64))[j - 16];
                __half2 h01 = __floats2half2_rn(f.x, f.y);
                __half2 h23 = __floats2half2_rn(f.z, f.w);
                uint2 u;
                u.x = *(uint32_t*)&h01; u.y = *(uint32_t*)&h23;
                Prow[j] = u;
            }
        }
        if (xt == 0) {
            const __half2 z = __floats2half2_rn(0.f, 0.f);
            const int erows[4] = {0, 1, 514, 515};
            const int prows[4] = {0, 513, 514, 515};
#pragma unroll
            for (int i = 0; i < 2; ++i) {
                int idx = tid + i * 256;
                ((__half2*)Eb)[(size_t)erows[idx >> 7] * 128 + (idx & 127)] = z;
            }
            ((__half2*)Pb)[(size_t)prows[tid >> 6] * 64 + (tid & 63)] = z;
        }
    }
}

// ---------------- fused pre: entity (block b) + batched corrections (k-group b) ----------------
__global__ void __launch_bounds__(256) pre_kernel(const int* __restrict__ sidx,
                                                  const int* __restrict__ oidx) {
    extern __shared__ float es[];                 // e0[64*256] | eL[64*256]
    float* e0s = es;
    float* eLs = es + 64 * 256;
    const int tid = threadIdx.x;                  // 256
    for (int idx = tid; idx < 64 * 256; idx += 256) {
        int bb = idx >> 8, e = idx & 255;
        e0s[idx] = __half2float(g_Eh[(size_t)bb * SR * EE + 2 * EE + e]);
        eLs[idx] = __half2float(g_Eh[(size_t)bb * SR * EE + 513 * EE + e]);
    }
    {
        const int b = blockIdx.x, e = tid;
        const __half* Eb = g_Eh + (size_t)b * SR * EE;
        for (int ent = 0; ent < 2; ++ent) {
            const int* ix = ent ? oidx : sidx;
            int s = ix[b * 2 + 0], en = ix[b * 2 + 1];
            int lo = s < 0 ? 0 : s;
            int hi = en > LL - 1 ? LL - 1 : en;
            float sum = 0.f; int cnt = 0;
            for (int l = lo; l <= hi; ++l) {
                sum += __half2float(Eb[(size_t)(l + 2) * EE + e]); ++cnt;
            }
            float mean = sum / (float)cnt;
            int li = s - 1; if (li < 0) li += LL;
            float left = __half2float(Eb[(size_t)(li + 2) * EE + e]);
            float right = 0.f;
            if (en + 1 < LL) {
                int ri = en + 1; if (ri < 0) ri = 0;
                right = __half2float(Eb[(size_t)(ri + 2) * EE + e]);
            }
            float* dst = g_com + (size_t)b * 2048 + ent * 768;
            dst[e] = mean; dst[256 + e] = left; dst[512 + e] = right;
        }
    }
    __syncthreads();
    const int w = tid >> 5, lane = tid & 31;
    const int k = blockIdx.x * 8 + w;
    float w0[8], wL[8];
#pragma unroll
    for (int q = 0; q < 8; ++q) {
        w0[q] = g_C0w[(size_t)k * EE + lane + q * 32];
        wL[q] = g_CLw[(size_t)k * EE + lane + q * 32];
    }
    for (int b = 0; b < 64; ++b) {
        float s0 = 0.f, sL = 0.f;
#pragma unroll
        for (int q = 0; q < 8; ++q) {
            s0 += e0s[b * 256 + lane + q * 32] * w0[q];
            sL += eLs[b * 256 + lane + q * 32] * wL[q];
        }
#pragma unroll
        for (int o = 16; o; o >>= 1) {
            s0 += __shfl_xor_sync(0xFFFFFFFFu, s0, o);
            sL += __shfl_xor_sync(0xFFFFFFFFu, sL, o);
        }
        if (lane == 0) {
            g_corr0[(size_t)b * KK + k] = s0;
            g_corrL[(size_t)b * KK + k] = sL;
        }
    }
}

// ---------------- fp16 mma conv + fused max-pool (4 warps, 64x64 warp tile) ----------------
__device__ __forceinline__ void stage_chunk(int gi, uint32_t sbase,
                                            const __half* Eb, const __half* Pb,
                                            int k0, int tid) {
    int l0 = (gi / NCH) * 128;
    int c  = gi % NCH;
    const __half* as; const __half* bs; int astr, bstr;
    if (c < 20) {
        int d = c >> 2, ec = c & 3;
        as = Eb + (size_t)(l0 + d) * EE + ec * 64;               astr = EE;
        bs = g_Wh + ((size_t)d * KK + k0) * EE + ec * 64;        bstr = EE;
    } else {
        int cc = c - 20, t = cc >> 1, pc = cc & 1;
        as = Pb + (size_t)(l0 + t) * PR + pc * 64;               astr = PR;
        bs = g_Wph + ((size_t)t * KK + k0) * PR + pc * 64;       bstr = PR;
    }
    const uint32_t st = sbase + (uint32_t)(gi % NST) * STAGE_B;
#pragma unroll
    for (int i = 0; i < 8; ++i) {
        int id = tid + i * 128;
        int r = id >> 3, c16 = id & 7;
        uint32_t off = SWZ((uint32_t)(r * 128 + c16 * 16));
        cpa16(st + off,         (const char*)(as + (size_t)r * astr) + c16 * 16);
        cpa16(st + 16384 + off, (const char*)(bs + (size_t)r * bstr) + c16 * 16);
    }
}

__global__ void __launch_bounds__(128, 2) conv_mma_kernel(const float* __restrict__ conv_b) {
    extern __shared__ char smem[];
    const uint32_t sbase = smem_u32(smem);
    float* red = (float*)(smem + NST * STAGE_B);
    const int tid = threadIdx.x, wid = tid >> 5, lane = tid & 31;
    const int lw = wid >> 1;          // 0..1 : 64 l-rows
    const int kw = wid & 1;           // 0..1 : 64 k-cols
    const int b = blockIdx.y, k0 = blockIdx.x * 128;
    const __half* Eb = g_Eh + (size_t)b * SR * EE;
    const __half* Pb = g_Ph + (size_t)b * SR * PR;

    const int rquad = lane >> 2, rlo = lane & 3;
    const int rowA = lw * 64 + (lane & 7) + ((lane >> 3) & 1) * 8;
    const int rowB = kw * 64 + (lane & 7) + ((lane >> 3) & 1) * 8;
    const int kbl  = (lane >> 4) * 16;

    float acc[4][8][4];
    float colmax[8][2];
#pragma unroll
    for (int nt = 0; nt < 8; ++nt) { colmax[nt][0] = -3.4e38f; colmax[nt][1] = -3.4e38f; }

    stage_chunk(0, sbase, Eb, Pb, k0, tid); CP_COMMIT();
    stage_chunk(1, sbase, Eb, Pb, k0, tid); CP_COMMIT();

    for (int gi = 0; gi < NGI; ++gi) {
        if (gi == NGI - 1) { CP_WAIT(0); } else { CP_WAIT(1); }
        __syncthreads();
        if (gi + 2 < NGI) { stage_chunk(gi + 2, sbase, Eb, Pb, k0, tid); CP_COMMIT(); }
        if (gi % NCH == 0) {
#pragma unroll
            for (int mt = 0; mt < 4; ++mt)
#pragma unroll
                for (int nt = 0; nt < 8; ++nt)
#pragma unroll
                    for (int j = 0; j < 4; ++j) acc[mt][nt][j] = 0.f;
        }
        const uint32_t sA = sbase + (uint32_t)(gi % NST) * STAGE_B;
        const uint32_t sB = sA + 16384;
#pragma unroll
        for (int ks = 0; ks < 4; ++ks) {
            uint32_t a[4][4], bf[4][4];
#pragma unroll
            for (int mt = 0; mt < 4; ++mt)
                ldsm4(a[mt], sA + SWZ((uint32_t)((rowA + mt * 16) * 128 + ks * 32 + kbl)));
#pragma unroll
            for (int bt = 0; bt < 4; ++bt)
                ldsm4(bf[bt], sB + SWZ((uint32_t)((rowB + bt * 16) * 128 + ks * 32 + kbl)));
#pragma unroll
            for (int mt = 0; mt < 4; ++mt)
#pragma unroll
                for (int bt = 0; bt < 4; ++bt) {
                    mma16816(acc[mt][bt * 2 + 0], a[mt], bf[bt][0], bf[bt][2]);
                    mma16816(acc[mt][bt * 2 + 1], a[mt], bf[bt][1], bf[bt][3]);
                }
        }
        if (gi % NCH == NCH - 1) {
            const int l0 = (gi / NCH) * 128;
            if (l0 == 0 && lw == 0 && rquad == 0) {        // global row 0
#pragma unroll
                for (int nt = 0; nt < 8; ++nt) {
                    int n = k0 + kw * 64 + nt * 8 + rlo * 2;
                    acc[0][nt][0] -= g_corr0[(size_t)b * KK + n];
                    acc[0][nt][1] -= g_corr0[(size_t)b * KK + n + 1];
                }
            }
            if (l0 == 384 && lw == 1 && rquad == 7) {      // global row 511
#pragma unroll
                for (int nt = 0; nt < 8; ++nt) {
                    int n = k0 + kw * 64 + nt * 8 + rlo * 2;
                    acc[3][nt][2] -= g_corrL[(size_t)b * KK + n];
                    acc[3][nt][3] -= g_corrL[(size_t)b * KK + n + 1];
                }
            }
#pragma unroll
            for (int mt = 0; mt < 4; ++mt)
#pragma unroll
                for (int nt = 0; nt < 8; ++nt) {
                    colmax[nt][0] = fmaxf(colmax[nt][0], fmaxf(acc[mt][nt][0], acc[mt][nt][2]));
                    colmax[nt][1] = fmaxf(colmax[nt][1], fmaxf(acc[mt][nt][1], acc[mt][nt][3]));
                }
        }
    }
#pragma unroll
    for (int nt = 0; nt < 8; ++nt)
#pragma unroll
        for (int j = 0; j < 2; ++j) {
            float v = colmax[nt][j];
            v = fmaxf(v, __shfl_xor_sync(0xFFFFFFFFu, v, 4));
            v = fmaxf(v, __shfl_xor_sync(0xFFFFFFFFu, v, 8));
            v = fmaxf(v, __shfl_xor_sync(0xFFFFFFFFu, v, 16));
            if (rquad == 0)
                red[lw * 128 + kw * 64 + nt * 8 + rlo * 2 + j] = v;
        }
    __syncthreads();
    if (tid < 128)
        g_pooled[(size_t)b * KK + k0 + tid] =
            fmaxf(red[tid], red[128 + tid]) + conv_b[k0 + tid];
}

// ---------------- lin1: 64x4 grid, smem pooled tile, 16 ILP accumulators ----------------
__global__ void __launch_bounds__(256) lin1_kernel(const float* __restrict__ w1,
                                                   const float* __restrict__ b1) {
    const int tid = threadIdx.x;
    const int w = tid >> 5, lane = tid & 31;
    const int h = blockIdx.x * 8 + w;             // 64 h-groups x 8 warps
    const int b0 = blockIdx.y * 16;               // 4 b-groups x 16 batches
    __shared__ float pt[16 * 512];                // 32KB
#pragma unroll
    for (int i = 0; i < 32; ++i) {
        int idx = tid + i * 256;
        pt[idx] = g_pooled[(size_t)(b0 + (idx >> 9)) * KK + (idx & 511)];
    }
    const float4* w4 = (const float4*)(w1 + (size_t)h * KK);
    float4 f[4];
#pragma unroll
    for (int q = 0; q < 4; ++q) f[q] = w4[lane + q * 32];
    __syncthreads();
    const float4* p4 = (const float4*)pt;
    float s[16];
#pragma unroll
    for (int i = 0; i < 16; ++i) s[i] = 0.f;
#pragma unroll
    for (int q = 0; q < 4; ++q) {
        int j = lane + q * 32;
#pragma unroll
        for (int i = 0; i < 16; ++i) {
            float4 g = p4[i * 128 + j];
            s[i] += f[q].x * g.x + f[q].y * g.y + f[q].z * g.z + f[q].w * g.w;
        }
    }
#pragma unroll
    for (int o = 16; o; o >>= 1)
#pragma unroll
        for (int i = 0; i < 16; ++i)
            s[i] += __shfl_xor_sync(0xFFFFFFFFu, s[i], o);
    if (lane == 0) {
        const float bb = b1[h];
#pragma unroll
        for (int i = 0; i < 16; ++i)
            g_com[(size_t)(b0 + i) * 2048 + 1536 + h] = tanhf(s[i] + bb);
    }
}

// ---------------- scores v3: grid (53, 8), one (t,b) dot per warp ----------------
__global__ void __launch_bounds__(256) scores_kernel(const float* __restrict__ w2,
                                                     const float* __restrict__ b2,
                                                     float* __restrict__ out) {
    const int t = blockIdx.x, tid = threadIdx.x;
    const int w = tid >> 5, lane = tid & 31;
    const int b = blockIdx.y * 8 + w;             // 8 b-groups x 8 warps
    __shared__ float wrow[2048];
    for (int i = tid; i < 2048; i += 256) wrow[i] = w2[(size_t)t * 2048 + i];
    __syncthreads();
    const float4* w4 = (const float4*)wrow;
    const float4* c4 = (const float4*)(g_com + (size_t)b * 2048);
    float s = 0.f;
#pragma unroll
    for (int q = 0; q < 16; ++q) {
        int j = lane + q * 32;
        float4 f = w4[j], g = c4[j];
        s += f.x * g.x + f.y * g.y + f.z * g.z + f.w * g.w;
    }
#pragma unroll
    for (int o = 16; o; o >>= 1) s += __shfl_xor_sync(0xFFFFFFFFu, s, o);
    if (lane == 0) out[(size_t)b * TT + t] = s + b2[t];
}

// ---------------- launch ----------------
extern "C" void kernel_launch(void* const* d_in, const int* in_sizes, int n_in,
                              void* d_out, int out_size) {
    const int*   context = (const int*)  d_in[0];
    const int*   sidx    = (const int*)  d_in[1];
    const int*   oidx    = (const int*)  d_in[2];
    const int*   sdis    = (const int*)  d_in[3];
    const int*   odis    = (const int*)  d_in[4];
    const float* etab    = (const float*)d_in[5];
    const float* ptab    = (const float*)d_in[6];
    const float* conv_w  = (const float*)d_in[7];
    const float* conv_b  = (const float*)d_in[8];
    const float* lin1_w  = (const float*)d_in[9];
    const float* lin1_b  = (const float*)d_in[10];
    const float* lin2_w  = (const float*)d_in[11];
    const float* lin2_b  = (const float*)d_in[12];
    float* out = (float*)d_out;

    cudaFuncSetAttribute(conv_mma_kernel,
                         cudaFuncAttributeMaxDynamicSharedMemorySize, SMEM_CONV);
    cudaFuncSetAttribute(pre_kernel,
                         cudaFuncAttributeMaxDynamicSharedMemorySize, SMEM_CORR);

    prep_kernel<<<1536, 256>>>(conv_w, context, sdis, odis, etab, ptab);
    pre_kernel<<<64, 256, SMEM_CORR>>>(sidx, oidx);
    conv_mma_kernel<<<dim3(4, BB), 128, SMEM_CONV>>>(conv_b);
    lin1_kernel<<<dim3(64, 4), 256>>>(lin1_w, lin1_b);
    scores_kernel<<<dim3(TT, 8), 256>>>(lin2_w, lin2_b, out);
}

// round 15
// speedup vs baseline: 1.2975x; 1.0261x over previous
#include <cuda_runtime.h>
#include <cuda_fp16.h>
#include <math.h>
#include <stdint.h>

#define BB   64
#define LL   512
#define EE   256
#define PR   128          // pos feature width (2*P)
#define KK   512
#define TT   53
#define SR   516          // padded rows (2-halo)
#define NCH  26           // K-chunks of 64 per l0 tile (20 embed + 6 pos)
#define NGI  (4 * NCH)    // flattened chunk count (4 l0 tiles)
#define NST  3            // stage slots
#define STAGE_B 32768     // A(16KB) + B(16KB) per chunk slot
// smem: stages | red(1KB) | corr(1KB) | e0/eL(2KB)
#define SMEM_CONV (NST * STAGE_B + 4096)

// ---------------- static device scratch ----------------
__device__ __align__(16) __half g_Eh[BB * SR * EE];    // [b][l+2][e] fp16
__device__ __align__(16) __half g_Ph[BB * SR * PR];    // [b][l+1][p] fp16
__device__ __align__(16) __half g_Wh[5 * KK * EE];     // [d][k][e] fp16
__device__ __align__(16) __half g_Wph[3 * KK * PR];    // [t][p][k] fp16
__device__ __align__(16) float  g_C0wT[EE * KK];       // [e][k] fp32 (transposed)
__device__ __align__(16) float  g_CLwT[EE * KK];       // [e][k] fp32 (transposed)
__device__ __align__(16) float  g_pooled[BB * KK];
__device__ __align__(16) float  g_com[BB * 2048];      // subj(768) obj(768) sent_h(512)

// ---------------- helpers ----------------
__device__ __forceinline__ uint32_t smem_u32(const void* p) {
    uint32_t a;
    asm("{ .reg .u64 t; cvta.to.shared.u64 t, %1; cvt.u32.u64 %0, t; }" : "=r"(a) : "l"(p));
    return a;
}
#define SWZ(off) ((off) ^ (((off) >> 3) & 0x70))
__device__ __forceinline__ void cpa16(uint32_t dst, const void* src) {
    asm volatile("cp.async.cg.shared.global [%0], [%1], 16;" :: "r"(dst), "l"(src) : "memory");
}
#define CP_COMMIT() asm volatile("cp.async.commit_group;" ::: "memory")
#define CP_WAIT(n)  asm volatile("cp.async.wait_group %0;" :: "n"(n) : "memory")
__device__ __forceinline__ void ldsm4(uint32_t* r, uint32_t addr) {
    asm volatile("ldmatrix.sync.aligned.m8n8.x4.shared.b16 {%0,%1,%2,%3}, [%4];"
                 : "=r"(r[0]), "=r"(r[1]), "=r"(r[2]), "=r"(r[3]) : "r"(addr));
}
__device__ __forceinline__ void mma16816(float* c, const uint32_t* a, uint32_t b0, uint32_t b1) {
    asm volatile("mma.sync.aligned.m16n8k16.row.col.f32.f16.f16.f32 "
                 "{%0,%1,%2,%3}, {%4,%5,%6,%7}, {%8,%9}, {%0,%1,%2,%3};"
                 : "+f"(c[0]), "+f"(c[1]), "+f"(c[2]), "+f"(c[3])
                 : "r"(a[0]), "r"(a[1]), "r"(a[2]), "r"(a[3]), "r"(b0), "r"(b1));
}

// ---------------- mega-prep: wprep [0,512) + gather [512,1536) + entity [1536,1600) ----------------
__global__ void __launch_bounds__(256) prep_kernel(const float* __restrict__ conv_w,
                                                   const int* __restrict__ context,
                                                   const int* __restrict__ sdis,
                                                   const int* __restrict__ odis,
                                                   const float* __restrict__ etab,
                                                   const float* __restrict__ ptab,
                                                   const int* __restrict__ sidx,
                                                   const int* __restrict__ oidx) {
    const int tid = threadIdx.x;
    if (blockIdx.x < 512) {
        // ---- weight fold+transpose: one block per k ----
        const int k = blockIdx.x;
        __shared__ float w[2688];
        const float* src = conv_w + (size_t)k * 2688;
        for (int i = tid; i < 2688; i += 256) w[i] = src[i];
        __syncthreads();
        const int e = tid;
#pragma unroll
        for (int d = 0; d < 5; ++d) {
            float s = 0.f;
#pragma unroll
            for (int j = 0; j < 3; ++j) {
                int t = d - j;
                if (t >= 0 && t < 3) s += w[(j * EE + e) * 3 + t];
            }
            g_Wh[((size_t)d * KK + k) * EE + e] = __float2half(s);
        }
        if (tid < PR) {
#pragma unroll
            for (int t = 0; t < 3; ++t)
                g_Wph[((size_t)t * KK + k) * PR + tid] = __float2half(w[(768 + tid) * 3 + t]);
        }
        g_C0wT[(size_t)e * KK + k] = w[(2 * EE + e) * 3 + 0];
        g_CLwT[(size_t)e * KK + k] = w[e * 3 + 2];
    } else if (blockIdx.x < 1536) {
        // ---- gather + halo zeroing ----
        const int bx = blockIdx.x - 512;
        const int b = bx >> 4, xt = bx & 15;
        const int grp = tid >> 5, lane = tid & 31;
        __half* Eb = g_Eh + (size_t)b * SR * EE;
        __half* Pb = g_Ph + (size_t)b * SR * PR;
#pragma unroll
        for (int li = 0; li < 4; ++li) {
            int l = xt * 32 + grp * 4 + li;
            int row = b * LL + l;
            int tok = context[row];
            const float4* es4 = (const float4*)(etab + (size_t)tok * EE);
            uint2* Erow = (uint2*)(Eb + (size_t)(l + 2) * EE);
#pragma unroll
            for (int it = 0; it < 2; ++it) {
                int j = it * 32 + lane;
                float4 f = es4[j];
                __half2 h01 = __floats2half2_rn(f.x, f.y);
                __half2 h23 = __floats2half2_rn(f.z, f.w);
                uint2 u;
                u.x = *(uint32_t*)&h01; u.y = *(uint32_t*)&h23;
                Erow[j] = u;
            }
            int ds = sdis[row], od = odis[row];
            uint2* Prow = (uint2*)(Pb + (size_t)(l + 1) * PR);
            {
                int j = lane;
                float4 f = (j < 16) ? ((const float4*)(ptab + (size_t)ds * 64))[j]
                                    : ((const float4*)(ptab + (size_t)od * 64))[j - 16];
                __half2 h01 = __floats2half2_rn(f.x, f.y);
                __half2 h23 = __floats2half2_rn(f.z, f.w);
                uint2 u;
                u.x = *(uint32_t*)&h01; u.y = *(uint32_t*)&h23;
                Prow[j] = u;
            }
        }
        if (xt == 0) {
            const __half2 z = __floats2half2_rn(0.f, 0.f);
            const int erows[4] = {0, 1, 514, 515};
            const int prows[4] = {0, 513, 514, 515};
#pragma unroll
            for (int i = 0; i < 2; ++i) {
                int idx = tid + i * 256;
                ((__half2*)Eb)[(size_t)erows[idx >> 7] * 128 + (idx & 127)] = z;
            }
            ((__half2*)Pb)[(size_t)prows[tid >> 6] * 64 + (tid & 63)] = z;
        }
    } else {
        // ---- entity features, straight from etab (independent of gather) ----
        const int b = blockIdx.x - 1536;
        const int e = tid;
        for (int ent = 0; ent < 2; ++ent) {
            const int* ix = ent ? oidx : sidx;
            int s = ix[b * 2 + 0], en = ix[b * 2 + 1];
            int lo = s < 0 ? 0 : s;
            int hi = en > LL - 1 ? LL - 1 : en;
            float sum = 0.f; int cnt = 0;
            for (int l = lo; l <= hi; ++l) {
                int tok = context[b * LL + l];
                sum += etab[(size_t)tok * EE + e]; ++cnt;
            }
            float mean = sum / (float)cnt;
            int li = s - 1; if (li < 0) li += LL;
            float left = etab[(size_t)context[b * LL + li] * EE + e];
            float right = 0.f;
            if (en + 1 < LL) {
                int ri = en + 1; if (ri < 0) ri = 0;
                right = etab[(size_t)context[b * LL + ri] * EE + e];
            }
            float* dst = g_com + (size_t)b * 2048 + ent * 768;
            dst[e] = mean; dst[256 + e] = left; dst[512 + e] = right;
        }
    }
}

// ---------------- fp16 mma conv + inline corr + fused max-pool ----------------
__device__ __forceinline__ void stage_chunk(int gi, uint32_t sbase,
                                            const __half* Eb, const __half* Pb,
                                            int k0, int tid) {
    int l0 = (gi / NCH) * 128;
    int c  = gi % NCH;
    const __half* as; const __half* bs; int astr, bstr;
    if (c < 20) {
        int d = c >> 2, ec = c & 3;
        as = Eb + (size_t)(l0 + d) * EE + ec * 64;               astr = EE;
        bs = g_Wh + ((size_t)d * KK + k0) * EE + ec * 64;        bstr = EE;
    } else {
        int cc = c - 20, t = cc >> 1, pc = cc & 1;
        as = Pb + (size_t)(l0 + t) * PR + pc * 64;               astr = PR;
        bs = g_Wph + ((size_t)t * KK + k0) * PR + pc * 64;       bstr = PR;
    }
    const uint32_t st = sbase + (uint32_t)(gi % NST) * STAGE_B;
#pragma unroll
    for (int i = 0; i < 8; ++i) {
        int id = tid + i * 128;
        int r = id >> 3, c16 = id & 7;
        uint32_t off = SWZ((uint32_t)(r * 128 + c16 * 16));
        cpa16(st + off,         (const char*)(as + (size_t)r * astr) + c16 * 16);
        cpa16(st + 16384 + off, (const char*)(bs + (size_t)r * bstr) + c16 * 16);
    }
}

__global__ void __launch_bounds__(128, 2) conv_mma_kernel(const float* __restrict__ conv_b) {
    extern __shared__ char smem[];
    const uint32_t sbase = smem_u32(smem);
    float* red    = (float*)(smem + NST * STAGE_B);          // 256 floats
    float* corr0s = (float*)(smem + NST * STAGE_B + 1024);   // 128 floats
    float* corrLs = corr0s + 128;                            // 128 floats
    float* e0s    = (float*)(smem + NST * STAGE_B + 2048);   // 256 floats
    float* eLs    = e0s + 256;                               // 256 floats
    const int tid = threadIdx.x, wid = tid >> 5, lane = tid & 31;
    const int lw = wid >> 1;          // 0..1 : 64 l-rows
    const int kw = wid & 1;           // 0..1 : 64 k-cols
    const int b = blockIdx.y, k0 = blockIdx.x * 128;
    const __half* Eb = g_Eh + (size_t)b * SR * EE;
    const __half* Pb = g_Ph + (size_t)b * SR * PR;

    const int rquad = lane >> 2, rlo = lane & 3;
    const int rowA = lw * 64 + (lane & 7) + ((lane >> 3) & 1) * 8;
    const int rowB = kw * 64 + (lane & 7) + ((lane >> 3) & 1) * 8;
    const int kbl  = (lane >> 4) * 16;

    float acc[4][8][4];
    float colmax[8][2];
#pragma unroll
    for (int nt = 0; nt < 8; ++nt) { colmax[nt][0] = -3.4e38f; colmax[nt][1] = -3.4e38f; }

    stage_chunk(0, sbase, Eb, Pb, k0, tid); CP_COMMIT();
    stage_chunk(1, sbase, Eb, Pb, k0, tid); CP_COMMIT();

    // ---- inline boundary corrections for this (b, k0..k0+127) slice ----
    {
#pragma unroll
        for (int i = 0; i < 2; ++i) {
            int e = tid + i * 128;
            e0s[e] = __half2float(Eb[2 * EE + e]);
            eLs[e] = __half2float(Eb[513 * EE + e]);
        }
        __syncthreads();
        float s0 = 0.f, sL = 0.f;
        const float* c0p = g_C0wT + k0 + tid;
        const float* cLp = g_CLwT + k0 + tid;
#pragma unroll 8
        for (int e = 0; e < EE; ++e) {
            s0 += e0s[e] * c0p[(size_t)e * KK];
            sL += eLs[e] * cLp[(size_t)e * KK];
        }
        corr0s[tid] = s0;
        corrLs[tid] = sL;
        // no barrier needed here: first read is at gi==25, behind many __syncthreads
    }

    for (int gi = 0; gi < NGI; ++gi) {
        if (gi == NGI - 1) { CP_WAIT(0); } else { CP_WAIT(1); }
        __syncthreads();
        if (gi + 2 < NGI) { stage_chunk(gi + 2, sbase, Eb, Pb, k0, tid); CP_COMMIT(); }
        if (gi % NCH == 0) {
#pragma unroll
            for (int mt = 0; mt < 4; ++mt)
#pragma unroll
                for (int nt = 0; nt < 8; ++nt)
#pragma unroll
                    for (int j = 0; j < 4; ++j) acc[mt][nt][j] = 0.f;
        }
        const uint32_t sA = sbase + (uint32_t)(gi % NST) * STAGE_B;
        const uint32_t sB = sA + 16384;
#pragma unroll
        for (int ks = 0; ks < 4; ++ks) {
            uint32_t a[4][4], bf[4][4];
#pragma unroll
            for (int mt = 0; mt < 4; ++mt)
                ldsm4(a[mt], sA + SWZ((uint32_t)((rowA + mt * 16) * 128 + ks * 32 + kbl)));
#pragma unroll
            for (int bt = 0; bt < 4; ++bt)
                ldsm4(bf[bt], sB + SWZ((uint32_t)((rowB + bt * 16) * 128 + ks * 32 + kbl)));
#pragma unroll
            for (int mt = 0; mt < 4; ++mt)
#pragma unroll
                for (int bt = 0; bt < 4; ++bt) {
                    mma16816(acc[mt][bt * 2 + 0], a[mt], bf[bt][0], bf[bt][2]);
                    mma16816(acc[mt][bt * 2 + 1], a[mt], bf[bt][1], bf[bt][3]);
                }
        }
        if (gi % NCH == NCH - 1) {
            const int l0 = (gi / NCH) * 128;
            if (l0 == 0 && lw == 0 && rquad == 0) {        // global row 0
#pragma unroll
                for (int nt = 0; nt < 8; ++nt) {
                    int n = kw * 64 + nt * 8 + rlo * 2;    // local k index
                    acc[0][nt][0] -= corr0s[n];
                    acc[0][nt][1] -= corr0s[n + 1];
                }
            }
            if (l0 == 384 && lw == 1 && rquad == 7) {      // global row 511
#pragma unroll
                for (int nt = 0; nt < 8; ++nt) {
                    int n = kw * 64 + nt * 8 + rlo * 2;
                    acc[3][nt][2] -= corrLs[n];
                    acc[3][nt][3] -= corrLs[n + 1];
                }
            }
#pragma unroll
            for (int mt = 0; mt < 4; ++mt)
#pragma unroll
                for (int nt = 0; nt < 8; ++nt) {
                    colmax[nt][0] = fmaxf(colmax[nt][0], fmaxf(acc[mt][nt][0], acc[mt][nt][2]));
                    colmax[nt][1] = fmaxf(colmax[nt][1], fmaxf(acc[mt][nt][1], acc[mt][nt][3]));
                }
        }
    }
#pragma unroll
    for (int nt = 0; nt < 8; ++nt)
#pragma unroll
        for (int j = 0; j < 2; ++j) {
            float v = colmax[nt][j];
            v = fmaxf(v, __shfl_xor_sync(0xFFFFFFFFu, v, 4));
            v = fmaxf(v, __shfl_xor_sync(0xFFFFFFFFu, v, 8));
            v = fmaxf(v, __shfl_xor_sync(0xFFFFFFFFu, v, 16));
            if (rquad == 0)
                red[lw * 128 + kw * 64 + nt * 8 + rlo * 2 + j] = v;
        }
    __syncthreads();
    if (tid < 128)
        g_pooled[(size_t)b * KK + k0 + tid] =
            fmaxf(red[tid], red[128 + tid]) + conv_b[k0 + tid];
}

// ---------------- lin1: 64x4 grid, smem pooled tile, 16 ILP accumulators ----------------
__global__ void __launch_bounds__(256) lin1_kernel(const float* __restrict__ w1,
                                                   const float* __restrict__ b1) {
    const int tid = threadIdx.x;
    const int w = tid >> 5, lane = tid & 31;
    const int h = blockIdx.x * 8 + w;             // 64 h-groups x 8 warps
    const int b0 = blockIdx.y * 16;               // 4 b-groups x 16 batches
    __shared__ float pt[16 * 512];                // 32KB
#pragma unroll
    for (int i = 0; i < 32; ++i) {
        int idx = tid + i * 256;
        pt[idx] = g_pooled[(size_t)(b0 + (idx >> 9)) * KK + (idx & 511)];
    }
    const float4* w4 = (const float4*)(w1 + (size_t)h * KK);
    float4 f[4];
#pragma unroll
    for (int q = 0; q < 4; ++q) f[q] = w4[lane + q * 32];
    __syncthreads();
    const float4* p4 = (const float4*)pt;
    float s[16];
#pragma unroll
    for (int i = 0; i < 16; ++i) s[i] = 0.f;
#pragma unroll
    for (int q = 0; q < 4; ++q) {
        int j = lane + q * 32;
#pragma unroll
        for (int i = 0; i < 16; ++i) {
            float4 g = p4[i * 128 + j];
            s[i] += f[q].x * g.x + f[q].y * g.y + f[q].z * g.z + f[q].w * g.w;
        }
    }
#pragma unroll
    for (int o = 16; o; o >>= 1)
#pragma unroll
        for (int i = 0; i < 16; ++i)
            s[i] += __shfl_xor_sync(0xFFFFFFFFu, s[i], o);
    if (lane == 0) {
        const float bb = b1[h];
#pragma unroll
        for (int i = 0; i < 16; ++i)
            g_com[(size_t)(b0 + i) * 2048 + 1536 + h] = tanhf(s[i] + bb);
    }
}

// ---------------- scores: grid (53, 8), one (t,b) dot per warp ----------------
__global__ void __launch_bounds__(256) scores_kernel(const float* __restrict__ w2,
                                                     const float* __restrict__ b2,
                                                     float* __restrict__ out) {
    const int t = blockIdx.x, tid = threadIdx.x;
    const int w = tid >> 5, lane = tid & 31;
    const int b = blockIdx.y * 8 + w;             // 8 b-groups x 8 warps
    __shared__ float wrow[2048];
    for (int i = tid; i < 2048; i += 256) wrow[i] = w2[(size_t)t * 2048 + i];
    __syncthreads();
    const float4* w4 = (const float4*)wrow;
    const float4* c4 = (const float4*)(g_com + (size_t)b * 2048);
    float s = 0.f;
#pragma unroll
    for (int q = 0; q < 16; ++q) {
        int j = lane + q * 32;
        float4 f = w4[j], g = c4[j];
        s += f.x * g.x + f.y * g.y + f.z * g.z + f.w * g.w;
    }
#pragma unroll
    for (int o = 16; o; o >>= 1) s += __shfl_xor_sync(0xFFFFFFFFu, s, o);
    if (lane == 0) out[(size_t)b * TT + t] = s + b2[t];
}

// ---------------- launch ----------------
extern "C" void kernel_launch(void* const* d_in, const int* in_sizes, int n_in,
                              void* d_out, int out_size) {
    const int*   context = (const int*)  d_in[0];
    const int*   sidx    = (const int*)  d_in[1];
    const int*   oidx    = (const int*)  d_in[2];
    const int*   sdis    = (const int*)  d_in[3];
    const int*   odis    = (const int*)  d_in[4];
    const float* etab    = (const float*)d_in[5];
    const float* ptab    = (const float*)d_in[6];
    const float* conv_w  = (const float*)d_in[7];
    const float* conv_b  = (const float*)d_in[8];
    const float* lin1_w  = (const float*)d_in[9];
    const float* lin1_b  = (const float*)d_in[10];
    const float* lin2_w  = (const float*)d_in[11];
    const float* lin2_b  = (const float*)d_in[12];
    float* out = (float*)d_out;

    cudaFuncSetAttribute(conv_mma_kernel,
                         cudaFuncAttributeMaxDynamicSharedMemorySize, SMEM_CONV);

    prep_kernel<<<1600, 256>>>(conv_w, context, sdis, odis, etab, ptab, sidx, oidx);
    conv_mma_kernel<<<dim3(4, BB), 128, SMEM_CONV>>>(conv_b);
    lin1_kernel<<<dim3(64, 4), 256>>>(lin1_w, lin1_b);
    scores_kernel<<<dim3(TT, 8), 256>>>(lin2_w, lin2_b, out);
}

// round 16
// speedup vs baseline: 1.3089x; 1.0088x over previous
#include <cuda_runtime.h>
#include <cuda_fp16.h>
#include <math.h>
#include <stdint.h>

#define BB   64
#define LL   512
#define EE   256
#define PR   128          // pos feature width (2*P)
#define KK   512
#define TT   53
#define SR   516          // padded rows (2-halo)
#define NGI2 128          // 4 tiles x 32 chunks
#define A_SLOT 17408      // 136 rows x 128B (132 used)
#define B_SLOT 16384
#define A0_OFF 0u
#define A1_OFF 17408u
#define B0_OFF 34816u
#define EX_OFF 83968u
#define SMEM_CONV (83968 + 4096)

// ---------------- static device scratch ----------------
__device__ __align__(16) __half g_Eh[BB * SR * EE];    // [b][l+2][e] fp16
__device__ __align__(16) __half g_Ph[BB * SR * PR];    // [b][l+1][p] fp16
__device__ __align__(16) __half g_Wh[5 * KK * EE];     // [d][k][e] fp16
__device__ __align__(16) __half g_Wph[3 * KK * PR];    // [t][k][p] fp16
__device__ __align__(16) float  g_C0wT[EE * KK];       // [e][k] fp32
__device__ __align__(16) float  g_CLwT[EE * KK];       // [e][k] fp32
__device__ __align__(16) float  g_pooled[BB * KK];
__device__ __align__(16) float  g_com[BB * 2048];      // subj(768) obj(768) sent_h(512)

// ---------------- helpers ----------------
__device__ __forceinline__ uint32_t smem_u32(const void* p) {
    uint32_t a;
    asm("{ .reg .u64 t; cvta.to.shared.u64 t, %1; cvt.u32.u64 %0, t; }" : "=r"(a) : "l"(p));
    return a;
}
#define SWZ(off) ((off) ^ (((off) >> 3) & 0x70))
__device__ __forceinline__ void cpa16(uint32_t dst, const void* src) {
    asm volatile("cp.async.cg.shared.global [%0], [%1], 16;" :: "r"(dst), "l"(src) : "memory");
}
#define CP_COMMIT() asm volatile("cp.async.commit_group;" ::: "memory")
#define CP_WAIT(n)  asm volatile("cp.async.wait_group %0;" :: "n"(n) : "memory")
__device__ __forceinline__ void ldsm4(uint32_t* r, uint32_t addr) {
    asm volatile("ldmatrix.sync.aligned.m8n8.x4.shared.b16 {%0,%1,%2,%3}, [%4];"
                 : "=r"(r[0]), "=r"(r[1]), "=r"(r[2]), "=r"(r[3]) : "r"(addr));
}
__device__ __forceinline__ void mma16816(float* c, const uint32_t* a, uint32_t b0, uint32_t b1) {
    asm volatile("mma.sync.aligned.m16n8k16.row.col.f32.f16.f16.f32 "
                 "{%0,%1,%2,%3}, {%4,%5,%6,%7}, {%8,%9}, {%0,%1,%2,%3};"
                 : "+f"(c[0]), "+f"(c[1]), "+f"(c[2]), "+f"(c[3])
                 : "r"(a[0]), "r"(a[1]), "r"(a[2]), "r"(a[3]), "r"(b0), "r"(b1));
}

// ---------------- mega-prep: wprep [0,512) + gather [512,1536) + entity [1536,1600) ----------------
__global__ void __launch_bounds__(256) prep_kernel(const float* __restrict__ conv_w,
                                                   const int* __restrict__ context,
                                                   const int* __restrict__ sdis,
                                                   const int* __restrict__ odis,
                                                   const float* __restrict__ etab,
                                                   const float* __restrict__ ptab,
                                                   const int* __restrict__ sidx,
                                                   const int* __restrict__ oidx) {
    const int tid = threadIdx.x;
    if (blockIdx.x < 512) {
        const int k = blockIdx.x;
        __shared__ float w[2688];
        const float* src = conv_w + (size_t)k * 2688;
        for (int i = tid; i < 2688; i += 256) w[i] = src[i];
        __syncthreads();
        const int e = tid;
#pragma unroll
        for (int d = 0; d < 5; ++d) {
            float s = 0.f;
#pragma unroll
            for (int j = 0; j < 3; ++j) {
                int t = d - j;
                if (t >= 0 && t < 3) s += w[(j * EE + e) * 3 + t];
            }
            g_Wh[((size_t)d * KK + k) * EE + e] = __float2half(s);
        }
        if (tid < PR) {
#pragma unroll
            for (int t = 0; t < 3; ++t)
                g_Wph[((size_t)t * KK + k) * PR + tid] = __float2half(w[(768 + tid) * 3 + t]);
        }
        g_C0wT[(size_t)e * KK + k] = w[(2 * EE + e) * 3 + 0];
        g_CLwT[(size_t)e * KK + k] = w[e * 3 + 2];
    } else if (blockIdx.x < 1536) {
        const int bx = blockIdx.x - 512;
        const int b = bx >> 4, xt = bx & 15;
        const int grp = tid >> 5, lane = tid & 31;
        __half* Eb = g_Eh + (size_t)b * SR * EE;
        __half* Pb = g_Ph + (size_t)b * SR * PR;
#pragma unroll
        for (int li = 0; li < 4; ++li) {
            int l = xt * 32 + grp * 4 + li;
            int row = b * LL + l;
            int tok = context[row];
            const float4* es4 = (const float4*)(etab + (size_t)tok * EE);
            uint2* Erow = (uint2*)(Eb + (size_t)(l + 2) * EE);
#pragma unroll
            for (int it = 0; it < 2; ++it) {
                int j = it * 32 + lane;
                float4 f = es4[j];
                __half2 h01 = __floats2half2_rn(f.x, f.y);
                __half2 h23 = __floats2half2_rn(f.z, f.w);
                uint2 u;
                u.x = *(uint32_t*)&h01; u.y = *(uint32_t*)&h23;
                Erow[j] = u;
            }
            int ds = sdis[row], od = odis[row];
            uint2* Prow = (uint2*)(Pb + (size_t)(l + 1) * PR);
            {
                int j = lane;
                float4 f = (j < 16) ? ((const float4*)(ptab + (size_t)ds * 64))[j]
                                    : ((const float4*)(ptab + (size_t)od * 64))[j - 16];
                __half2 h01 = __floats2half2_rn(f.x, f.y);
                __half2 h23 = __floats2half2_rn(f.z, f.w);
                uint2 u;
                u.x = *(uint32_t*)&h01; u.y = *(uint32_t*)&h23;
                Prow[j] = u;
            }
        }
        if (xt == 0) {
            const __half2 z = __floats2half2_rn(0.f, 0.f);
            const int erows[4] = {0, 1, 514, 515};
            const int prows[4] = {0, 513, 514, 515};
#pragma unroll
            for (int i = 0; i < 2; ++i) {
                int idx = tid + i * 256;
                ((__half2*)Eb)[(size_t)erows[idx >> 7] * 128 + (idx & 127)] = z;
            }
            ((__half2*)Pb)[(size_t)prows[tid >> 6] * 64 + (tid & 63)] = z;
        }
    } else {
        // entity features, straight from etab
        const int b = blockIdx.x - 1536;
        const int e = tid;
        for (int ent = 0; ent < 2; ++ent) {
            const int* ix = ent ? oidx : sidx;
            int s = ix[b * 2 + 0], en = ix[b * 2 + 1];
            int lo = s < 0 ? 0 : s;
            int hi = en > LL - 1 ? LL - 1 : en;
            float sum = 0.f; int cnt = 0;
            for (int l = lo; l <= hi; ++l) {
                int tok = context[b * LL + l];
                sum += etab[(size_t)tok * EE + e]; ++cnt;
            }
            float mean = sum / (float)cnt;
            int li = s - 1; if (li < 0) li += LL;
            float left = etab[(size_t)context[b * LL + li] * EE + e];
            float right = 0.f;
            if (en + 1 < LL) {
                int ri = en + 1; if (ri < 0) ri = 0;
                right = etab[(size_t)context[b * LL + ri] * EE + e];
            }
            float* dst = g_com + (size_t)b * 2048 + ent * 768;
            dst[e] = mean; dst[256 + e] = left; dst[512 + e] = right;
        }
    }
}

// ---------------- conv staging (A staged once per (l0,chunk); tap shift in LDSM row) ----------------
__device__ __forceinline__ void stage_Ae(uint32_t dst, const __half* Eb, int l0, int ec, int tid) {
#pragma unroll
    for (int i = 0; i < 9; ++i) {
        int id = tid + i * 128;
        if (id < 132 * 8) {
            int r = id >> 3, c16 = id & 7;
            cpa16(dst + SWZ((uint32_t)(r * 128 + c16 * 16)),
                  (const char*)(Eb + (size_t)(l0 + r) * EE + ec * 64) + c16 * 16);
        }
    }
}
__device__ __forceinline__ void stage_Ap(uint32_t dst, const __half* Pb, int l0, int pc, int tid) {
#pragma unroll
    for (int i = 0; i < 9; ++i) {
        int id = tid + i * 128;
        if (id < 130 * 8) {
            int r = id >> 3, c16 = id & 7;
            cpa16(dst + SWZ((uint32_t)(r * 128 + c16 * 16)),
                  (const char*)(Pb + (size_t)(l0 + r) * PR + pc * 64) + c16 * 16);
        }
    }
}
__device__ __forceinline__ void stage_B(uint32_t dst, const __half* bs, int bstr, int tid) {
#pragma unroll
    for (int i = 0; i < 8; ++i) {
        int id = tid + i * 128;
        int r = id >> 3, c16 = id & 7;
        cpa16(dst + SWZ((uint32_t)(r * 128 + c16 * 16)),
              (const char*)(bs + (size_t)r * bstr) + c16 * 16);
    }
}

__device__ __forceinline__ void stage_chunk2(int gi, uint32_t sbase,
                                             const __half* Eb, const __half* Pb,
                                             int k0, int tid) {
    const int tile = gi >> 5, c = gi & 31, l0 = tile << 7;
    if (c < 24) {
        int g = c / 6, r = c - g * 6;
        if (r == 0) stage_Ae(sbase + ((g & 1) ? A1_OFF : A0_OFF), Eb, l0, g, tid);
        else {
            int bidx = tile * 26 + g * 5 + (r - 1);
            stage_B(sbase + B0_OFF + (uint32_t)(bidx % 3) * B_SLOT,
                    g_Wh + ((size_t)(r - 1) * KK + k0) * EE + g * 64, EE, tid);
        }
    } else {
        int c2 = c - 24, g = c2 >> 2, r = c2 & 3;
        if (r == 0) stage_Ap(sbase + ((g & 1) ? A1_OFF : A0_OFF), Pb, l0, g, tid);
        else {
            int bidx = tile * 26 + 20 + g * 3 + (r - 1);
            stage_B(sbase + B0_OFF + (uint32_t)(bidx % 3) * B_SLOT,
                    g_Wph + ((size_t)(r - 1) * KK + k0) * PR + g * 64, PR, tid);
        }
    }
}

__global__ void __launch_bounds__(128, 2) conv_mma_kernel(const float* __restrict__ conv_b) {
    extern __shared__ char smem[];
    const uint32_t sbase = smem_u32(smem);
    float* red    = (float*)(smem + EX_OFF);          // 256 floats
    float* corr0s = (float*)(smem + EX_OFF + 1024);   // 128
    float* corrLs = corr0s + 128;                     // 128
    float* e0s    = (float*)(smem + EX_OFF + 2048);   // 256
    float* eLs    = e0s + 256;                        // 256
    const int tid = threadIdx.x, wid = tid >> 5, lane = tid & 31;
    const int lw = wid >> 1;          // 0..1 : 64 l-rows
    const int kw = wid & 1;           // 0..1 : 64 k-cols
    const int b = blockIdx.y, k0 = blockIdx.x * 128;
    const __half* Eb = g_Eh + (size_t)b * SR * EE;
    const __half* Pb = g_Ph + (size_t)b * SR * PR;

    const int rquad = lane >> 2, rlo = lane & 3;
    const int rowA = lw * 64 + (lane & 7) + ((lane >> 3) & 1) * 8;
    const int rowB = kw * 64 + (lane & 7) + ((lane >> 3) & 1) * 8;
    const int kbl  = (lane >> 4) * 16;

    float acc[4][8][4];
    float colmax[8][2];
#pragma unroll
    for (int nt = 0; nt < 8; ++nt) { colmax[nt][0] = -3.4e38f; colmax[nt][1] = -3.4e38f; }

    stage_chunk2(0, sbase, Eb, Pb, k0, tid); CP_COMMIT();
    stage_chunk2(1, sbase, Eb, Pb, k0, tid); CP_COMMIT();

    // ---- inline boundary corrections for this (b, k-slice) ----
    {
#pragma unroll
        for (int i = 0; i < 2; ++i) {
            int e = tid + i * 128;
            e0s[e] = __half2float(Eb[2 * EE + e]);
            eLs[e] = __half2float(Eb[513 * EE + e]);
        }
        __syncthreads();
        float s0 = 0.f, sL = 0.f;
        const float* c0p = g_C0wT + k0 + tid;
        const float* cLp = g_CLwT + k0 + tid;
#pragma unroll 8
        for (int e = 0; e < EE; ++e) {
            s0 += e0s[e] * c0p[(size_t)e * KK];
            sL += eLs[e] * cLp[(size_t)e * KK];
        }
        corr0s[tid] = s0;
        corrLs[tid] = sL;
    }

    for (int gi = 0; gi < NGI2; ++gi) {
        if (gi == NGI2 - 1) { CP_WAIT(0); } else { CP_WAIT(1); }
        __syncthreads();
        if (gi + 2 < NGI2) { stage_chunk2(gi + 2, sbase, Eb, Pb, k0, tid); CP_COMMIT(); }

        const int tile = gi >> 5, c = gi & 31;
        if (c == 0) {
#pragma unroll
            for (int mt = 0; mt < 4; ++mt)
#pragma unroll
                for (int nt = 0; nt < 8; ++nt)
#pragma unroll
                    for (int j = 0; j < 4; ++j) acc[mt][nt][j] = 0.f;
        }

        // decode: is this a B chunk? which slots / shift?
        int isB = 0, dshift = 0;
        uint32_t aOff = 0, bOff = 0;
        if (c < 24) {
            int g = c / 6, r = c - g * 6;
            if (r != 0) {
                isB = 1; dshift = r - 1;
                aOff = (g & 1) ? A1_OFF : A0_OFF;
                int bidx = tile * 26 + g * 5 + (r - 1);
                bOff = B0_OFF + (uint32_t)(bidx % 3) * B_SLOT;
            }
        } else {
            int c2 = c - 24, g = c2 >> 2, r = c2 & 3;
            if (r != 0) {
                isB = 1; dshift = r - 1;
                aOff = (g & 1) ? A1_OFF : A0_OFF;
                int bidx = tile * 26 + 20 + g * 3 + (r - 1);
                bOff = B0_OFF + (uint32_t)(bidx % 3) * B_SLOT;
            }
        }

        if (isB) {
            const uint32_t sA = sbase + aOff;
            const uint32_t sB = sbase + bOff;
#pragma unroll
            for (int ks = 0; ks < 4; ++ks) {
                uint32_t a[4][4], bf[4][4];
#pragma unroll
                for (int mt = 0; mt < 4; ++mt)
                    ldsm4(a[mt], sA + SWZ((uint32_t)((rowA + mt * 16 + dshift) * 128
                                                     + ks * 32 + kbl)));
#pragma unroll
                for (int bt = 0; bt < 4; ++bt)
                    ldsm4(bf[bt], sB + SWZ((uint32_t)((rowB + bt * 16) * 128 + ks * 32 + kbl)));
#pragma unroll
                for (int mt = 0; mt < 4; ++mt)
#pragma unroll
                    for (int bt = 0; bt < 4; ++bt) {
                        mma16816(acc[mt][bt * 2 + 0], a[mt], bf[bt][0], bf[bt][2]);
                        mma16816(acc[mt][bt * 2 + 1], a[mt], bf[bt][1], bf[bt][3]);
                    }
            }
        }

        if (c == 31) {
            const int l0 = tile << 7;
            if (l0 == 0 && lw == 0 && rquad == 0) {        // global row 0
#pragma unroll
                for (int nt = 0; nt < 8; ++nt) {
                    int n = kw * 64 + nt * 8 + rlo * 2;
                    acc[0][nt][0] -= corr0s[n];
                    acc[0][nt][1] -= corr0s[n + 1];
                }
            }
            if (l0 == 384 && lw == 1 && rquad == 7) {      // global row 511
#pragma unroll
                for (int nt = 0; nt < 8; ++nt) {
                    int n = kw * 64 + nt * 8 + rlo * 2;
                    acc[3][nt][2] -= corrLs[n];
                    acc[3][nt][3] -= corrLs[n + 1];
                }
            }
#pragma unroll
            for (int mt = 0; mt < 4; ++mt)
#pragma unroll
                for (int nt = 0; nt < 8; ++nt) {
                    colmax[nt][0] = fmaxf(colmax[nt][0], fmaxf(acc[mt][nt][0], acc[mt][nt][2]));
                    colmax[nt][1] = fmaxf(colmax[nt][1], fmaxf(acc[mt][nt][1], acc[mt][nt][3]));
                }
        }
    }
#pragma unroll
    for (int nt = 0; nt < 8; ++nt)
#pragma unroll
        for (int j = 0; j < 2; ++j) {
            float v = colmax[nt][j];
            v = fmaxf(v, __shfl_xor_sync(0xFFFFFFFFu, v, 4));
            v = fmaxf(v, __shfl_xor_sync(0xFFFFFFFFu, v, 8));
            v = fmaxf(v, __shfl_xor_sync(0xFFFFFFFFu, v, 16));
            if (rquad == 0)
                red[lw * 128 + kw * 64 + nt * 8 + rlo * 2 + j] = v;
        }
    __syncthreads();
    if (tid < 128)
        g_pooled[(size_t)b * KK + k0 + tid] =
            fmaxf(red[tid], red[128 + tid]) + conv_b[k0 + tid];
}

// ---------------- lin1: 64x4 grid, smem pooled tile, 16 ILP accumulators ----------------
__global__ void __launch_bounds__(256) lin1_kernel(const float* __restrict__ w1,
                                                   const float* __restrict__ b1) {
    const int tid = threadIdx.x;
    const int w = tid >> 5, lane = tid & 31;
    const int h = blockIdx.x * 8 + w;
    const int b0 = blockIdx.y * 16;
    __shared__ float pt[16 * 512];
#pragma unroll
    for (int i = 0; i < 32; ++i) {
        int idx = tid + i * 256;
        pt[idx] = g_pooled[(size_t)(b0 + (idx >> 9)) * KK + (idx & 511)];
    }
    const float4* w4 = (const float4*)(w1 + (size_t)h * KK);
    float4 f[4];
#pragma unroll
    for (int q = 0; q < 4; ++q) f[q] = w4[lane + q * 32];
    __syncthreads();
    const float4* p4 = (const float4*)pt;
    float s[16];
#pragma unroll
    for (int i = 0; i < 16; ++i) s[i] = 0.f;
#pragma unroll
    for (int q = 0; q < 4; ++q) {
        int j = lane + q * 32;
#pragma unroll
        for (int i = 0; i < 16; ++i) {
            float4 g = p4[i * 128 + j];
            s[i] += f[q].x * g.x + f[q].y * g.y + f[q].z * g.z + f[q].w * g.w;
        }
    }
#pragma unroll
    for (int o = 16; o; o >>= 1)
#pragma unroll
        for (int i = 0; i < 16; ++i)
            s[i] += __shfl_xor_sync(0xFFFFFFFFu, s[i], o);
    if (lane == 0) {
        const float bb = b1[h];
#pragma unroll
        for (int i = 0; i < 16; ++i)
            g_com[(size_t)(b0 + i) * 2048 + 1536 + h] = tanhf(s[i] + bb);
    }
}

// ---------------- scores: grid (53, 8), one (t,b) dot per warp ----------------
__global__ void __launch_bounds__(256) scores_kernel(const float* __restrict__ w2,
                                                     const float* __restrict__ b2,
                                                     float* __restrict__ out) {
    const int t = blockIdx.x, tid = threadIdx.x;
    const int w = tid >> 5, lane = tid & 31;
    const int b = blockIdx.y * 8 + w;
    __shared__ float wrow[2048];
    for (int i = tid; i < 2048; i += 256) wrow[i] = w2[(size_t)t * 2048 + i];
    __syncthreads();
    const float4* w4 = (const float4*)wrow;
    const float4* c4 = (const float4*)(g_com + (size_t)b * 2048);
    float s = 0.f;
#pragma unroll
    for (int q = 0; q < 16; ++q) {
        int j = lane + q * 32;
        float4 f = w4[j], g = c4[j];
        s += f.x * g.x + f.y * g.y + f.z * g.z + f.w * g.w;
    }
#pragma unroll
    for (int o = 16; o; o >>= 1) s += __shfl_xor_sync(0xFFFFFFFFu, s, o);
    if (lane == 0) out[(size_t)b * TT + t] = s + b2[t];
}

// ---------------- launch ----------------
extern "C" void kernel_launch(void* const* d_in, const int* in_sizes, int n_in,
                              void* d_out, int out_size) {
    const int*   context = (const int*)  d_in[0];
    const int*   sidx    = (const int*)  d_in[1];
    const int*   oidx    = (const int*)  d_in[2];
    const int*   sdis    = (const int*)  d_in[3];
    const int*   odis    = (const int*)  d_in[4];
    const float* etab    = (const float*)d_in[5];
    const float* ptab    = (const float*)d_in[6];
    const float* conv_w  = (const float*)d_in[7];
    const float* conv_b  = (const float*)d_in[8];
    const float* lin1_w  = (const float*)d_in[9];
    const float* lin1_b  = (const float*)d_in[10];
    const float* lin2_w  = (const float*)d_in[11];
    const float* lin2_b  = (const float*)d_in[12];
    float* out = (float*)d_out;

    cudaFuncSetAttribute(conv_mma_kernel,
                         cudaFuncAttributeMaxDynamicSharedMemorySize, SMEM_CONV);

    prep_kernel<<<1600, 256>>>(conv_w, context, sdis, odis, etab, ptab, sidx, oidx);
    conv_mma_kernel<<<dim3(4, BB), 128, SMEM_CONV>>>(conv_b);
    lin1_kernel<<<dim3(64, 4), 256>>>(lin1_w, lin1_b);
    scores_kernel<<<dim3(TT, 8), 256>>>(lin2_w, lin2_b, out);
}

// round 17
// speedup vs baseline: 1.3219x; 1.0099x over previous
#include <cuda_runtime.h>
#include <cuda_fp16.h>
#include <math.h>
#include <stdint.h>

#define BB   64
#define LL   512
#define EE   256
#define PR   128          // pos feature width (2*P)
#define KK   512
#define TT   53
#define SR   516          // padded rows (2-halo)
#define NCH3 26           // chunks per l0 tile (A merged into lead chunk)
#define NGI3 104          // 4 tiles x 26 chunks
#define A_SLOT 17408      // 136 rows x 128B (132 used)
#define B_SLOT 16384
#define A0_OFF 0u
#define A1_OFF 17408u
#define B0_OFF 34816u
#define EX_OFF 83968u
#define SMEM_CONV (83968 + 4096)

// ---------------- static device scratch ----------------
__device__ __align__(16) __half g_Eh[BB * SR * EE];    // [b][l+2][e] fp16
__device__ __align__(16) __half g_Ph[BB * SR * PR];    // [b][l+1][p] fp16
__device__ __align__(16) __half g_Wh[5 * KK * EE];     // [d][k][e] fp16
__device__ __align__(16) __half g_Wph[3 * KK * PR];    // [t][k][p] fp16
__device__ __align__(16) float  g_C0wT[EE * KK];       // [e][k] fp32
__device__ __align__(16) float  g_CLwT[EE * KK];       // [e][k] fp32
__device__ __align__(16) float  g_pooled[BB * KK];
__device__ __align__(16) float  g_com[BB * 2048];      // subj(768) obj(768) sent_h(512)

// ---------------- helpers ----------------
__device__ __forceinline__ uint32_t smem_u32(const void* p) {
    uint32_t a;
    asm("{ .reg .u64 t; cvta.to.shared.u64 t, %1; cvt.u32.u64 %0, t; }" : "=r"(a) : "l"(p));
    return a;
}
#define SWZ(off) ((off) ^ (((off) >> 3) & 0x70))
__device__ __forceinline__ void cpa16(uint32_t dst, const void* src) {
    asm volatile("cp.async.cg.shared.global [%0], [%1], 16;" :: "r"(dst), "l"(src) : "memory");
}
#define CP_COMMIT() asm volatile("cp.async.commit_group;" ::: "memory")
#define CP_WAIT(n)  asm volatile("cp.async.wait_group %0;" :: "n"(n) : "memory")
__device__ __forceinline__ void ldsm4(uint32_t* r, uint32_t addr) {
    asm volatile("ldmatrix.sync.aligned.m8n8.x4.shared.b16 {%0,%1,%2,%3}, [%4];"
                 : "=r"(r[0]), "=r"(r[1]), "=r"(r[2]), "=r"(r[3]) : "r"(addr));
}
__device__ __forceinline__ void mma16816(float* c, const uint32_t* a, uint32_t b0, uint32_t b1) {
    asm volatile("mma.sync.aligned.m16n8k16.row.col.f32.f16.f16.f32 "
                 "{%0,%1,%2,%3}, {%4,%5,%6,%7}, {%8,%9}, {%0,%1,%2,%3};"
                 : "+f"(c[0]), "+f"(c[1]), "+f"(c[2]), "+f"(c[3])
                 : "r"(a[0]), "r"(a[1]), "r"(a[2]), "r"(a[3]), "r"(b0), "r"(b1));
}

// ---------------- mega-prep: wprep [0,512) + gather [512,1536) + entity [1536,1600) ----------------
__global__ void __launch_bounds__(256) prep_kernel(const float* __restrict__ conv_w,
                                                   const int* __restrict__ context,
                                                   const int* __restrict__ sdis,
                                                   const int* __restrict__ odis,
                                                   const float* __restrict__ etab,
                                                   const float* __restrict__ ptab,
                                                   const int* __restrict__ sidx,
                                                   const int* __restrict__ oidx) {
    const int tid = threadIdx.x;
    if (blockIdx.x < 512) {
        const int k = blockIdx.x;
        __shared__ float w[2688];
        const float* src = conv_w + (size_t)k * 2688;
        for (int i = tid; i < 2688; i += 256) w[i] = src[i];
        __syncthreads();
        const int e = tid;
#pragma unroll
        for (int d = 0; d < 5; ++d) {
            float s = 0.f;
#pragma unroll
            for (int j = 0; j < 3; ++j) {
                int t = d - j;
                if (t >= 0 && t < 3) s += w[(j * EE + e) * 3 + t];
            }
            g_Wh[((size_t)d * KK + k) * EE + e] = __float2half(s);
        }
        if (tid < PR) {
#pragma unroll
            for (int t = 0; t < 3; ++t)
                g_Wph[((size_t)t * KK + k) * PR + tid] = __float2half(w[(768 + tid) * 3 + t]);
        }
        g_C0wT[(size_t)e * KK + k] = w[(2 * EE + e) * 3 + 0];
        g_CLwT[(size_t)e * KK + k] = w[e * 3 + 2];
    } else if (blockIdx.x < 1536) {
        const int bx = blockIdx.x - 512;
        const int b = bx >> 4, xt = bx & 15;
        const int grp = tid >> 5, lane = tid & 31;
        __half* Eb = g_Eh + (size_t)b * SR * EE;
        __half* Pb = g_Ph + (size_t)b * SR * PR;
#pragma unroll
        for (int li = 0; li < 4; ++li) {
            int l = xt * 32 + grp * 4 + li;
            int row = b * LL + l;
            int tok = context[row];
            const float4* es4 = (const float4*)(etab + (size_t)tok * EE);
            uint2* Erow = (uint2*)(Eb + (size_t)(l + 2) * EE);
#pragma unroll
            for (int it = 0; it < 2; ++it) {
                int j = it * 32 + lane;
                float4 f = es4[j];
                __half2 h01 = __floats2half2_rn(f.x, f.y);
                __half2 h23 = __floats2half2_rn(f.z, f.w);
                uint2 u;
                u.x = *(uint32_t*)&h01; u.y = *(uint32_t*)&h23;
                Erow[j] = u;
            }
            int ds = sdis[row], od = odis[row];
            uint2* Prow = (uint2*)(Pb + (size_t)(l + 1) * PR);
            {
                int j = lane;
                float4 f = (j < 16) ? ((const float4*)(ptab + (size_t)ds * 64))[j]
                                    : ((const float4*)(ptab + (size_t)od * 64))[j - 16];
                __half2 h01 = __floats2half2_rn(f.x, f.y);
                __half2 h23 = __floats2half2_rn(f.z, f.w);
                uint2 u;
                u.x = *(uint32_t*)&h01; u.y = *(uint32_t*)&h23;
                Prow[j] = u;
            }
        }
        if (xt == 0) {
            const __half2 z = __floats2half2_rn(0.f, 0.f);
            const int erows[4] = {0, 1, 514, 515};
            const int prows[4] = {0, 513, 514, 515};
#pragma unroll
            for (int i = 0; i < 2; ++i) {
                int idx = tid + i * 256;
                ((__half2*)Eb)[(size_t)erows[idx >> 7] * 128 + (idx & 127)] = z;
            }
            ((__half2*)Pb)[(size_t)prows[tid >> 6] * 64 + (tid & 63)] = z;
        }
    } else {
        // entity features, straight from etab
        const int b = blockIdx.x - 1536;
        const int e = tid;
        for (int ent = 0; ent < 2; ++ent) {
            const int* ix = ent ? oidx : sidx;
            int s = ix[b * 2 + 0], en = ix[b * 2 + 1];
            int lo = s < 0 ? 0 : s;
            int hi = en > LL - 1 ? LL - 1 : en;
            float sum = 0.f; int cnt = 0;
            for (int l = lo; l <= hi; ++l) {
                int tok = context[b * LL + l];
                sum += etab[(size_t)tok * EE + e]; ++cnt;
            }
            float mean = sum / (float)cnt;
            int li = s - 1; if (li < 0) li += LL;
            float left = etab[(size_t)context[b * LL + li] * EE + e];
            float right = 0.f;
            if (en + 1 < LL) {
                int ri = en + 1; if (ri < 0) ri = 0;
                right = etab[(size_t)context[b * LL + ri] * EE + e];
            }
            float* dst = g_com + (size_t)b * 2048 + ent * 768;
            dst[e] = mean; dst[256 + e] = left; dst[512 + e] = right;
        }
    }
}

// ---------------- conv staging ----------------
__device__ __forceinline__ void stage_Ae(uint32_t dst, const __half* Eb, int l0, int ec, int tid) {
#pragma unroll
    for (int i = 0; i < 9; ++i) {
        int id = tid + i * 128;
        if (id < 132 * 8) {
            int r = id >> 3, c16 = id & 7;
            cpa16(dst + SWZ((uint32_t)(r * 128 + c16 * 16)),
                  (const char*)(Eb + (size_t)(l0 + r) * EE + ec * 64) + c16 * 16);
        }
    }
}
__device__ __forceinline__ void stage_Ap(uint32_t dst, const __half* Pb, int l0, int pc, int tid) {
#pragma unroll
    for (int i = 0; i < 9; ++i) {
        int id = tid + i * 128;
        if (id < 130 * 8) {
            int r = id >> 3, c16 = id & 7;
            cpa16(dst + SWZ((uint32_t)(r * 128 + c16 * 16)),
                  (const char*)(Pb + (size_t)(l0 + r) * PR + pc * 64) + c16 * 16);
        }
    }
}
__device__ __forceinline__ void stage_B(uint32_t dst, const __half* bs, int bstr, int tid) {
#pragma unroll
    for (int i = 0; i < 8; ++i) {
        int id = tid + i * 128;
        int r = id >> 3, c16 = id & 7;
        cpa16(dst + SWZ((uint32_t)(r * 128 + c16 * 16)),
              (const char*)(bs + (size_t)r * bstr) + c16 * 16);
    }
}

// merged schedule: per tile 26 chunks; A staged with the group-leading chunk
__device__ __forceinline__ void stage_chunk3(int gi, uint32_t sbase,
                                             const __half* Eb, const __half* Pb,
                                             int k0, int tid) {
    const int tile = gi / NCH3, c = gi - tile * NCH3, l0 = tile << 7;
    const uint32_t bOff = B0_OFF + (uint32_t)(gi % 3) * B_SLOT;
    if (c < 20) {
        int g = c / 5, r = c - g * 5;
        if (r == 0) stage_Ae(sbase + ((g & 1) ? A1_OFF : A0_OFF), Eb, l0, g, tid);
        stage_B(sbase + bOff, g_Wh + ((size_t)r * KK + k0) * EE + g * 64, EE, tid);
    } else {
        int c2 = c - 20, gp = c2 / 3, r = c2 - gp * 3;   // gp: 0,1 -> groups 4,5
        if (r == 0) stage_Ap(sbase + (((4 + gp) & 1) ? A1_OFF : A0_OFF), Pb, l0, gp, tid);
        stage_B(sbase + bOff, g_Wph + ((size_t)r * KK + k0) * PR + gp * 64, PR, tid);
    }
}

__global__ void __launch_bounds__(128, 2) conv_mma_kernel(const float* __restrict__ conv_b) {
    extern __shared__ char smem[];
    const uint32_t sbase = smem_u32(smem);
    float* red    = (float*)(smem + EX_OFF);          // 256 floats
    float* corr0s = (float*)(smem + EX_OFF + 1024);   // 128
    float* corrLs = corr0s + 128;                     // 128
    float* e0s    = (float*)(smem + EX_OFF + 2048);   // 256
    float* eLs    = e0s + 256;                        // 256
    const int tid = threadIdx.x, wid = tid >> 5, lane = tid & 31;
    const int lw = wid >> 1;          // 0..1 : 64 l-rows
    const int kw = wid & 1;           // 0..1 : 64 k-cols
    const int b = blockIdx.y, k0 = blockIdx.x * 128;
    const __half* Eb = g_Eh + (size_t)b * SR * EE;
    const __half* Pb = g_Ph + (size_t)b * SR * PR;

    const int rquad = lane >> 2, rlo = lane & 3;
    const int rowA = lw * 64 + (lane & 7) + ((lane >> 3) & 1) * 8;
    const int rowB = kw * 64 + (lane & 7) + ((lane >> 3) & 1) * 8;
    const int kbl  = (lane >> 4) * 16;

    float acc[4][8][4];
    float colmax[8][2];
#pragma unroll
    for (int nt = 0; nt < 8; ++nt) { colmax[nt][0] = -3.4e38f; colmax[nt][1] = -3.4e38f; }

    stage_chunk3(0, sbase, Eb, Pb, k0, tid); CP_COMMIT();
    stage_chunk3(1, sbase, Eb, Pb, k0, tid); CP_COMMIT();

    // ---- inline boundary corrections for this (b, k-slice) ----
    {
#pragma unroll
        for (int i = 0; i < 2; ++i) {
            int e = tid + i * 128;
            e0s[e] = __half2float(Eb[2 * EE + e]);
            eLs[e] = __half2float(Eb[513 * EE + e]);
        }
        __syncthreads();
        float s0 = 0.f, sL = 0.f;
        const float* c0p = g_C0wT + k0 + tid;
        const float* cLp = g_CLwT + k0 + tid;
#pragma unroll 8
        for (int e = 0; e < EE; ++e) {
            s0 += e0s[e] * c0p[(size_t)e * KK];
            sL += eLs[e] * cLp[(size_t)e * KK];
        }
        corr0s[tid] = s0;
        corrLs[tid] = sL;
    }

    for (int gi = 0; gi < NGI3; ++gi) {
        if (gi == NGI3 - 1) { CP_WAIT(0); } else { CP_WAIT(1); }
        __syncthreads();
        if (gi + 2 < NGI3) { stage_chunk3(gi + 2, sbase, Eb, Pb, k0, tid); CP_COMMIT(); }

        const int tile = gi / NCH3, c = gi - tile * NCH3;
        if (c == 0) {
#pragma unroll
            for (int mt = 0; mt < 4; ++mt)
#pragma unroll
                for (int nt = 0; nt < 8; ++nt)
#pragma unroll
                    for (int j = 0; j < 4; ++j) acc[mt][nt][j] = 0.f;
        }

        // decode A slot + tap shift for this chunk
        int g, dshift;
        if (c < 20) { g = c / 5; dshift = c - g * 5; }
        else        { int c2 = c - 20; int gp = c2 / 3; g = 4 + gp; dshift = c2 - gp * 3; }
        const uint32_t sA = sbase + ((g & 1) ? A1_OFF : A0_OFF);
        const uint32_t sB = sbase + B0_OFF + (uint32_t)(gi % 3) * B_SLOT;

#pragma unroll
        for (int ks = 0; ks < 4; ++ks) {
            uint32_t a[4][4], bf[4][4];
#pragma unroll
            for (int mt = 0; mt < 4; ++mt)
                ldsm4(a[mt], sA + SWZ((uint32_t)((rowA + mt * 16 + dshift) * 128
                                                 + ks * 32 + kbl)));
#pragma unroll
            for (int bt = 0; bt < 4; ++bt)
                ldsm4(bf[bt], sB + SWZ((uint32_t)((rowB + bt * 16) * 128 + ks * 32 + kbl)));
#pragma unroll
            for (int mt = 0; mt < 4; ++mt)
#pragma unroll
                for (int bt = 0; bt < 4; ++bt) {
                    mma16816(acc[mt][bt * 2 + 0], a[mt], bf[bt][0], bf[bt][2]);
                    mma16816(acc[mt][bt * 2 + 1], a[mt], bf[bt][1], bf[bt][3]);
                }
        }

        if (c == NCH3 - 1) {
            const int l0 = tile << 7;
            if (l0 == 0 && lw == 0 && rquad == 0) {        // global row 0
#pragma unroll
                for (int nt = 0; nt < 8; ++nt) {
                    int n = kw * 64 + nt * 8 + rlo * 2;
                    acc[0][nt][0] -= corr0s[n];
                    acc[0][nt][1] -= corr0s[n + 1];
                }
            }
            if (l0 == 384 && lw == 1 && rquad == 7) {      // global row 511
#pragma unroll
                for (int nt = 0; nt < 8; ++nt) {
                    int n = kw * 64 + nt * 8 + rlo * 2;
                    acc[3][nt][2] -= corrLs[n];
                    acc[3][nt][3] -= corrLs[n + 1];
                }
            }
#pragma unroll
            for (int mt = 0; mt < 4; ++mt)
#pragma unroll
                for (int nt = 0; nt < 8; ++nt) {
                    colmax[nt][0] = fmaxf(colmax[nt][0], fmaxf(acc[mt][nt][0], acc[mt][nt][2]));
                    colmax[nt][1] = fmaxf(colmax[nt][1], fmaxf(acc[mt][nt][1], acc[mt][nt][3]));
                }
        }
    }
#pragma unroll
    for (int nt = 0; nt < 8; ++nt)
#pragma unroll
        for (int j = 0; j < 2; ++j) {
            float v = colmax[nt][j];
            v = fmaxf(v, __shfl_xor_sync(0xFFFFFFFFu, v, 4));
            v = fmaxf(v, __shfl_xor_sync(0xFFFFFFFFu, v, 8));
            v = fmaxf(v, __shfl_xor_sync(0xFFFFFFFFu, v, 16));
            if (rquad == 0)
                red[lw * 128 + kw * 64 + nt * 8 + rlo * 2 + j] = v;
        }
    __syncthreads();
    if (tid < 128)
        g_pooled[(size_t)b * KK + k0 + tid] =
            fmaxf(red[tid], red[128 + tid]) + conv_b[k0 + tid];
}

// ---------------- lin1: 64x4 grid, smem pooled tile, 16 ILP accumulators ----------------
__global__ void __launch_bounds__(256) lin1_kernel(const float* __restrict__ w1,
                                                   const float* __restrict__ b1) {
    const int tid = threadIdx.x;
    const int w = tid >> 5, lane = tid & 31;
    const int h = blockIdx.x * 8 + w;
    const int b0 = blockIdx.y * 16;
    __shared__ float pt[16 * 512];
#pragma unroll
    for (int i = 0; i < 32; ++i) {
        int idx = tid + i * 256;
        pt[idx] = g_pooled[(size_t)(b0 + (idx >> 9)) * KK + (idx & 511)];
    }
    const float4* w4 = (const float4*)(w1 + (size_t)h * KK);
    float4 f[4];
#pragma unroll
    for (int q = 0; q < 4; ++q) f[q] = w4[lane + q * 32];
    __syncthreads();
    const float4* p4 = (const float4*)pt;
    float s[16];
#pragma unroll
    for (int i = 0; i < 16; ++i) s[i] = 0.f;
#pragma unroll
    for (int q = 0; q < 4; ++q) {
        int j = lane + q * 32;
#pragma unroll
        for (int i = 0; i < 16; ++i) {
            float4 g = p4[i * 128 + j];
            s[i] += f[q].x * g.x + f[q].y * g.y + f[q].z * g.z + f[q].w * g.w;
        }
    }
#pragma unroll
    for (int o = 16; o; o >>= 1)
#pragma unroll
        for (int i = 0; i < 16; ++i)
            s[i] += __shfl_xor_sync(0xFFFFFFFFu, s[i], o);
    if (lane == 0) {
        const float bb = b1[h];
#pragma unroll
        for (int i = 0; i < 16; ++i)
            g_com[(size_t)(b0 + i) * 2048 + 1536 + h] = tanhf(s[i] + bb);
    }
}

// ---------------- scores: grid (53, 8), one (t,b) dot per warp ----------------
__global__ void __launch_bounds__(256) scores_kernel(const float* __restrict__ w2,
                                                     const float* __restrict__ b2,
                                                     float* __restrict__ out) {
    const int t = blockIdx.x, tid = threadIdx.x;
    const int w = tid >> 5, lane = tid & 31;
    const int b = blockIdx.y * 8 + w;
    __shared__ float wrow[2048];
    for (int i = tid; i < 2048; i += 256) wrow[i] = w2[(size_t)t * 2048 + i];
    __syncthreads();
    const float4* w4 = (const float4*)wrow;
    const float4* c4 = (const float4*)(g_com + (size_t)b * 2048);
    float s = 0.f;
#pragma unroll
    for (int q = 0; q < 16; ++q) {
        int j = lane + q * 32;
        float4 f = w4[j], g = c4[j];
        s += f.x * g.x + f.y * g.y + f.z * g.z + f.w * g.w;
    }
#pragma unroll
    for (int o = 16; o; o >>= 1) s += __shfl_xor_sync(0xFFFFFFFFu, s, o);
    if (lane == 0) out[(size_t)b * TT + t] = s + b2[t];
}

// ---------------- launch ----------------
extern "C" void kernel_launch(void* const* d_in, const int* in_sizes, int n_in,
                              void* d_out, int out_size) {
    const int*   context = (const int*)  d_in[0];
    const int*   sidx    = (const int*)  d_in[1];
    const int*   oidx    = (const int*)  d_in[2];
    const int*   sdis    = (const int*)  d_in[3];
    const int*   odis    = (const int*)  d_in[4];
    const float* etab    = (const float*)d_in[5];
    const float* ptab    = (const float*)d_in[6];
    const float* conv_w  = (const float*)d_in[7];
    const float* conv_b  = (const float*)d_in[8];
    const float* lin1_w  = (const float*)d_in[9];
    const float* lin1_b  = (const float*)d_in[10];
    const float* lin2_w  = (const float*)d_in[11];
    const float* lin2_b  = (const float*)d_in[12];
    float* out = (float*)d_out;

    cudaFuncSetAttribute(conv_mma_kernel,
                         cudaFuncAttributeMaxDynamicSharedMemorySize, SMEM_CONV);

    prep_kernel<<<1600, 256>>>(conv_w, context, sdis, odis, etab, ptab, sidx, oidx);
    conv_mma_kernel<<<dim3(4, BB), 128, SMEM_CONV>>>(conv_b);
    lin1_kernel<<<dim3(64, 4), 256>>>(lin1_w, lin1_b);
    scores_kernel<<<dim3(TT, 8), 256>>>(lin2_w, lin2_b, out);
}